// round 11
// baseline (speedup 1.0000x reference)
#include <cuda_runtime.h>
#include <mma.h>
using namespace nvcuda;

#define BB 2
#define SS 2048
#define HH 768
#define NH 12
#define DD 64
#define BH (BB*NH)
#define M_PROJ (BB*SS)
#define OUT_ELEMS (BB*SS*HH)
#define ATTN_ELEMS ((size_t)BB*NH*SS*SS)

__device__ float g_qh[BB*NH*SS*DD];
__device__ float g_kh[BB*NH*SS*DD];
__device__ float g_vh[BB*NH*SS*DD];
__device__ float g_ctx[BB*SS*HH];
__device__ float g_cpart[2][BB*SS*HH];   // unnormalized partial AV per K-half
__device__ float g_lpart[2][BH*SS];      // partial exp-sums per K-half
__device__ float g_attn_scratch[BB*NH*SS*SS];

typedef wmma::fragment<wmma::matrix_a, 16, 16, 8, wmma::precision::tf32, wmma::row_major> FragA;
typedef wmma::fragment<wmma::matrix_b, 16, 16, 8, wmma::precision::tf32, wmma::col_major> FragBc;
typedef wmma::fragment<wmma::matrix_b, 16, 16, 8, wmma::precision::tf32, wmma::row_major> FragBr;
typedef wmma::fragment<wmma::accumulator, 16, 16, 8, float> FragC;

#define LDS 36           // 32-k slab + 4 pad (proj kernel)
#define SLABK 32
#define NSLAB (HH/SLABK) // 24
#define LDP 68           // 64 + 4
#define LDQ 132          // 128 + 4
#define LDT 20           // 16-k slab + 4 pad (out_proj kernel)
#define KHALF 1024       // K columns per attention CTA
#define QROWS 64         // Q rows per attention CTA (3 CTA/SM)

// log2-domain softmax: p = 2^(s * 0.125*log2(e) + b2); masked b2 = -100
#define SC_L2E 0.18033688011112042f
#define MASK_B2 (-100.0f)

#define CVT4(t4) do { \
    t4.x = wmma::__float_to_tf32(t4.x); t4.y = wmma::__float_to_tf32(t4.y); \
    t4.z = wmma::__float_to_tf32(t4.z); t4.w = wmma::__float_to_tf32(t4.w); } while(0)

__device__ __forceinline__ float exp2_mufu(float y) {
    float r;
    asm("ex2.approx.f32 %0, %1;" : "=f"(r) : "f"(y));
    return r;
}

// ============================================================
// Kernel 1: fused QKV projections (128x128 tile, 32-k slab).
// ============================================================
__global__ void __launch_bounds__(256, 2)
proj_qkv_kernel(const float* __restrict__ q,
                const float* __restrict__ k,
                const float* __restrict__ v,
                const float* __restrict__ Wq, const float* __restrict__ bq,
                const float* __restrict__ Wk, const float* __restrict__ bk,
                const float* __restrict__ Wv, const float* __restrict__ bv) {
    const float* X; const float* W; const float* bias; float* Y;
    if (blockIdx.z == 0)      { X = q; W = Wq; bias = bq; Y = g_qh; }
    else if (blockIdx.z == 1) { X = k; W = Wk; bias = bk; Y = g_kh; }
    else                      { X = v; W = Wv; bias = bv; Y = g_vh; }

    extern __shared__ float sm[];
    float* As = sm;
    float* Bs = sm + 128 * LDS;
    float* Cs = sm;
    __shared__ float bias_s[128];

    const int tid = threadIdx.x;
    const int w = tid >> 5;
    const int m0 = blockIdx.y * 128, n0 = blockIdx.x * 128;
    const int wm = (w & 1) * 64, wn = (w >> 1) * 32;
    if (tid < 128) bias_s[tid] = bias[n0 + tid];

    FragC acc[4][2];
    #pragma unroll
    for (int i = 0; i < 4; i++)
        #pragma unroll
        for (int j = 0; j < 2; j++) wmma::fill_fragment(acc[i][j], 0.0f);

    const int r = tid >> 1;
    const int c0 = (tid & 1) * 16;
    const float* xp = X + (size_t)(m0 + r) * HH + c0;
    const float* wp = W + (size_t)(n0 + r) * HH + c0;

    for (int s = 0; s < NSLAB; s++) {
        #pragma unroll
        for (int i = 0; i < 4; i++) {
            float4 t4 = *(const float4*)(xp + s * SLABK + i * 4);
            CVT4(t4); *(float4*)&As[r * LDS + c0 + i * 4] = t4;
            float4 u4 = *(const float4*)(wp + s * SLABK + i * 4);
            CVT4(u4); *(float4*)&Bs[r * LDS + c0 + i * 4] = u4;
        }
        __syncthreads();
        #pragma unroll
        for (int kk = 0; kk < 4; kk++) {
            FragA a[4]; FragBc b[2];
            #pragma unroll
            for (int i = 0; i < 4; i++) wmma::load_matrix_sync(a[i], &As[(wm + i * 16) * LDS + kk * 8], LDS);
            #pragma unroll
            for (int j = 0; j < 2; j++) wmma::load_matrix_sync(b[j], &Bs[(wn + j * 16) * LDS + kk * 8], LDS);
            #pragma unroll
            for (int i = 0; i < 4; i++)
                #pragma unroll
                for (int j = 0; j < 2; j++) wmma::mma_sync(acc[i][j], a[i], b[j], acc[i][j]);
        }
        __syncthreads();
    }

    #pragma unroll
    for (int i = 0; i < 4; i++)
        #pragma unroll
        for (int j = 0; j < 2; j++)
            wmma::store_matrix_sync(&Cs[(wm + i * 16) * LDQ + wn + j * 16], acc[i][j], LDQ, wmma::mem_row_major);
    __syncthreads();

    {
        const int rr = tid >> 1;
        const int cc = (tid & 1) * 64;
        const int h = (n0 + cc) >> 6;
        const int m = m0 + rr, b = m >> 11, s = m & 2047;
        float* dst = &Y[(((size_t)b * NH + h) * SS + s) * DD];
        #pragma unroll
        for (int t = 0; t < 16; t++) {
            float4 t4 = *(float4*)&Cs[rr * LDQ + cc + t * 4];
            t4.x += bias_s[cc + t * 4];     t4.y += bias_s[cc + t * 4 + 1];
            t4.z += bias_s[cc + t * 4 + 2]; t4.w += bias_s[cc + t * 4 + 3];
            *(float4*)&dst[t * 4] = t4;
        }
    }
}

// ============================================================
// Kernel 2: fused attention, K-split 2-way, 64-row Q tiles,
// 3 CTA/SM. Mask read directly from gmem (L2-hot).
// ============================================================
__global__ void __launch_bounds__(256, 3)
fused_attn_kernel(const int* __restrict__ mask, float* __restrict__ attn) {
    extern __shared__ float sm[];
    float* Qs = sm;                    // [QROWS][LDP]
    float* Ks = Qs + QROWS * LDP;      // [64][LDP]
    float* Vs = Ks + 64 * LDP;         // [64][LDP]
    float* ps = Vs + 64 * LDP;         // [QROWS][LDP]

    const int tid = threadIdx.x;
    const int w = tid >> 5;
    const int bh = blockIdx.y;
    const int b = bh / NH, h = bh % NH;
    const int m0 = blockIdx.x * QROWS;
    const int half = blockIdx.z;
    const int kbase = half * KHALF;
    const int wm = (w >> 1) * 16, wn = (w & 1) * 32;

    const float* qh_head = g_qh + (size_t)bh * SS * DD + (size_t)m0 * DD;
    const float* kh_head = g_kh + (size_t)bh * SS * DD;
    const float* vh_head = g_vh + (size_t)bh * SS * DD;
    const int* mrow = mask + b * SS + kbase;

    // load Q tile (tf32): 64 rows x 64 cols
    {
        int r = tid >> 2, cc = (tid & 3) * 16;
        #pragma unroll
        for (int i = 0; i < 4; i++) {
            float4 t4 = *(const float4*)&qh_head[(size_t)r * DD + cc + i * 4];
            CVT4(t4);
            *(float4*)&Qs[r * LDP + cc + i * 4] = t4;
        }
    }
    __syncthreads();

    const int erow = tid >> 2;         // 0..63
    const int cb   = (tid & 2) ? ((tid & 1) * 4 + 8) : ((tid & 1) * 4); // 0,4,8,12
    float l_run = 0.0f;

    FragC accv[2];
    wmma::fill_fragment(accv[0], 0.0f);
    wmma::fill_fragment(accv[1], 0.0f);

    float* arow = attn + ((size_t)bh * SS + m0 + erow) * SS + kbase;

    for (int cl = 0; cl < KHALF; cl += 64) {
        const int c0 = kbase + cl;
        // ---- load K + V chunk (tf32) ----
        {
            int kr = tid >> 2, cc = (tid & 3) * 16;
            const float* ksrc = kh_head + (size_t)(c0 + kr) * DD + cc;
            const float* vsrc = vh_head + (size_t)(c0 + kr) * DD + cc;
            #pragma unroll
            for (int i = 0; i < 4; i++) {
                float4 t4 = *(const float4*)(ksrc + i * 4);
                CVT4(t4); *(float4*)&Ks[kr * LDP + cc + i * 4] = t4;
                float4 u4 = *(const float4*)(vsrc + i * 4);
                CVT4(u4); *(float4*)&Vs[kr * LDP + cc + i * 4] = u4;
            }
        }
        __syncthreads();

        // ---- S = Q @ K^T (64x64) ----
        {
            FragC sa[2];
            wmma::fill_fragment(sa[0], 0.0f);
            wmma::fill_fragment(sa[1], 0.0f);
            #pragma unroll
            for (int kk = 0; kk < 8; kk++) {
                FragA a0; FragBc b0, b1;
                wmma::load_matrix_sync(a0, &Qs[wm * LDP + kk * 8], LDP);
                wmma::load_matrix_sync(b0, &Ks[(wn +  0) * LDP + kk * 8], LDP);
                wmma::load_matrix_sync(b1, &Ks[(wn + 16) * LDP + kk * 8], LDP);
                wmma::mma_sync(sa[0], a0, b0, sa[0]);
                wmma::mma_sync(sa[1], a0, b1, sa[1]);
            }
            wmma::store_matrix_sync(&ps[wm * LDP + wn +  0], sa[0], LDP, wmma::mem_row_major);
            wmma::store_matrix_sync(&ps[wm * LDP + wn + 16], sa[1], LDP, wmma::mem_row_major);
        }
        __syncthreads();

        // ---- p = 2^(s*SC_L2E + b2); write unnormalized attn ----
        {
            float lsum = 0.0f;
            #pragma unroll
            for (int i = 0; i < 4; i++) {
                int c = cb + i * 16;
                float4 t4 = *(float4*)&ps[erow * LDP + c];
                int4 mm = *(const int4*)&mrow[cl + c];
                float4 p4;
                p4.x = exp2_mufu(fmaf(t4.x, SC_L2E, mm.x ? MASK_B2 : 0.0f));
                p4.y = exp2_mufu(fmaf(t4.y, SC_L2E, mm.y ? MASK_B2 : 0.0f));
                p4.z = exp2_mufu(fmaf(t4.z, SC_L2E, mm.z ? MASK_B2 : 0.0f));
                p4.w = exp2_mufu(fmaf(t4.w, SC_L2E, mm.w ? MASK_B2 : 0.0f));
                lsum += p4.x + p4.y + p4.z + p4.w;
                *(float4*)&arow[cl + c] = p4;   // unnormalized attn (coalesced quads)
                CVT4(p4);
                *(float4*)&ps[erow * LDP + c] = p4;
            }
            l_run += lsum;
        }
        __syncthreads();

        // ---- AV accumulate: accv += P(64x64) @ V(64x64) ----
        #pragma unroll
        for (int kk = 0; kk < 8; kk++) {
            FragA a0; FragBr b0, b1;
            wmma::load_matrix_sync(a0, &ps[wm * LDP + kk * 8], LDP);
            wmma::load_matrix_sync(b0, &Vs[(kk * 8) * LDP + wn +  0], LDP);
            wmma::load_matrix_sync(b1, &Vs[(kk * 8) * LDP + wn + 16], LDP);
            wmma::mma_sync(accv[0], a0, b0, accv[0]);
            wmma::mma_sync(accv[1], a0, b1, accv[1]);
        }
        __syncthreads();
    }

    // row sum across the 4 threads of this row (lanes 4k..4k+3)
    l_run += __shfl_xor_sync(0xFFFFFFFFu, l_run, 1);
    l_run += __shfl_xor_sync(0xFFFFFFFFu, l_run, 2);
    if ((tid & 3) == 0) g_lpart[half][bh * SS + m0 + erow] = l_run;

    wmma::store_matrix_sync(&ps[wm * LDP + wn +  0], accv[0], LDP, wmma::mem_row_major);
    wmma::store_matrix_sync(&ps[wm * LDP + wn + 16], accv[1], LDP, wmma::mem_row_major);
    __syncthreads();
    {
        float* dst = &g_cpart[half][((size_t)(b * SS + m0 + erow)) * HH + h * 64];
        #pragma unroll
        for (int i = 0; i < 4; i++) {
            int c = cb + i * 16;
            float4 t4 = *(float4*)&ps[erow * LDP + c];
            *(float4*)&dst[c] = t4;   // unnormalized partial
        }
    }
}

// ============================================================
// Kernel 3: combine partial AV halves: ctx = (P0+P1)/(l0+l1).
// ============================================================
__global__ void __launch_bounds__(192)
combine_ctx_kernel() {
    const int row = blockIdx.x;           // b*SS + s
    const int b = row >> 11, s = row & 2047;
    __shared__ float inv_s[NH];
    if (threadIdx.x < NH) {
        int li = (b * NH + threadIdx.x) * SS + s;
        inv_s[threadIdx.x] = 1.0f / (g_lpart[0][li] + g_lpart[1][li]);
    }
    __syncthreads();
    const int n = threadIdx.x * 4;
    const float inv = inv_s[n >> 6];
    const size_t base = (size_t)row * HH + n;
    float4 a = *(const float4*)&g_cpart[0][base];
    float4 c = *(const float4*)&g_cpart[1][base];
    a.x = (a.x + c.x) * inv; a.y = (a.y + c.y) * inv;
    a.z = (a.z + c.z) * inv; a.w = (a.w + c.w) * inv;
    *(float4*)&g_ctx[base] = a;
}

// ============================================================
// Kernel 4: attn rescale (block per row, coalesced streaming).
// ============================================================
__global__ void __launch_bounds__(256)
attn_scale_kernel(float* __restrict__ attn) {
    const int row = blockIdx.x;
    const float inv = 1.0f / (g_lpart[0][row] + g_lpart[1][row]);
    float* p = attn + (size_t)row * SS;
    const int t = threadIdx.x;
    #pragma unroll
    for (int i = 0; i < 2; i++) {
        int c = (t + i * 256) * 4;
        float4 v4 = *(float4*)&p[c];
        v4.x *= inv; v4.y *= inv; v4.z *= inv; v4.w *= inv;
        *(float4*)&p[c] = v4;
    }
}

// ============================================================
// Kernel 5: out = ctx @ Wm^T + bm (128x64 tile, 16-k slab).
// ============================================================
__global__ void __launch_bounds__(256)
out_proj_kernel(const float* __restrict__ Wm,
                const float* __restrict__ bm,
                float* __restrict__ out) {
    __shared__ float sbuf[128 * LDP];
    __shared__ float bias_s[64];
    float* As = sbuf;
    float* Bs = sbuf + 128 * LDT;
    float* Cs = sbuf;

    const int tid = threadIdx.x;
    const int w = tid >> 5;
    const int m0 = blockIdx.y * 128, n0 = blockIdx.x * 64;
    const int mw = (w >> 1) * 32, nw = (w & 1) * 32;
    if (tid < 64) bias_s[tid] = bm[n0 + tid];

    FragC acc[2][2];
    #pragma unroll
    for (int i = 0; i < 2; i++)
        #pragma unroll
        for (int j = 0; j < 2; j++) wmma::fill_fragment(acc[i][j], 0.0f);

    for (int k0 = 0; k0 < HH; k0 += 16) {
        #pragma unroll
        for (int jj = 0; jj < 2; jj++) {
            int e = tid + 256 * jj;
            int r = e >> 2, c4 = (e & 3) * 4;
            float4 t4 = *(const float4*)&g_ctx[(size_t)(m0 + r) * HH + k0 + c4];
            CVT4(t4);
            *(float4*)&As[r * LDT + c4] = t4;
        }
        {
            int r = tid >> 2, c4 = (tid & 3) * 4;
            float4 t4 = *(const float4*)&Wm[(size_t)(n0 + r) * HH + k0 + c4];
            CVT4(t4);
            *(float4*)&Bs[r * LDT + c4] = t4;
        }
        __syncthreads();
        #pragma unroll
        for (int kt = 0; kt < 2; kt++) {
            FragA a0, a1; FragBc b0, b1;
            wmma::load_matrix_sync(a0, &As[(mw +  0) * LDT + kt * 8], LDT);
            wmma::load_matrix_sync(a1, &As[(mw + 16) * LDT + kt * 8], LDT);
            wmma::load_matrix_sync(b0, &Bs[(nw +  0) * LDT + kt * 8], LDT);
            wmma::load_matrix_sync(b1, &Bs[(nw + 16) * LDT + kt * 8], LDT);
            wmma::mma_sync(acc[0][0], a0, b0, acc[0][0]);
            wmma::mma_sync(acc[0][1], a0, b1, acc[0][1]);
            wmma::mma_sync(acc[1][0], a1, b0, acc[1][0]);
            wmma::mma_sync(acc[1][1], a1, b1, acc[1][1]);
        }
        __syncthreads();
    }
    #pragma unroll
    for (int i = 0; i < 2; i++)
        #pragma unroll
        for (int j = 0; j < 2; j++)
            wmma::store_matrix_sync(&Cs[(mw + i * 16) * LDP + nw + j * 16], acc[i][j], LDP, wmma::mem_row_major);
    __syncthreads();

    #pragma unroll
    for (int jj = 0; jj < 8; jj++) {
        int e = tid + 256 * jj;
        int r = e >> 4, c4 = (e & 15) * 4;
        float4 t4 = *(float4*)&Cs[r * LDP + c4];
        t4.x += bias_s[c4]; t4.y += bias_s[c4 + 1];
        t4.z += bias_s[c4 + 2]; t4.w += bias_s[c4 + 3];
        *(float4*)&out[(size_t)(m0 + r) * HH + n0 + c4] = t4;
    }
}

// ============================================================
// Host launcher — attn_scale overlapped with combine+out_proj.
// ============================================================
extern "C" void kernel_launch(void* const* d_in, const int* in_sizes, int n_in,
                              void* d_out, int out_size) {
    const float* v    = (const float*)d_in[0];
    const float* k    = (const float*)d_in[1];
    const float* q    = (const float*)d_in[2];
    const int*   mask = (const int*)  d_in[3];
    const float* Wv   = (const float*)d_in[4];
    const float* bv   = (const float*)d_in[5];
    const float* Wk   = (const float*)d_in[6];
    const float* bk   = (const float*)d_in[7];
    const float* Wq   = (const float*)d_in[8];
    const float* bq   = (const float*)d_in[9];
    const float* Wm   = (const float*)d_in[10];
    const float* bm   = (const float*)d_in[11];
    float* out = (float*)d_out;

    float* attn;
    if ((size_t)out_size >= (size_t)OUT_ELEMS + ATTN_ELEMS) {
        attn = out + OUT_ELEMS;
    } else {
        void* p = nullptr;
        cudaGetSymbolAddress(&p, g_attn_scratch);
        attn = (float*)p;
    }

    const int SMEM_GEMM = 128 * LDQ * 4;                                    // 67584
    const int SMEM_FA   = (QROWS * LDP + 64 * LDP + 64 * LDP + QROWS * LDP) * 4; // 69632
    static int init_done = 0;
    static cudaStream_t s2;
    static cudaEvent_t ev_fork, ev_join;
    if (!init_done) {
        cudaFuncSetAttribute(proj_qkv_kernel, cudaFuncAttributeMaxDynamicSharedMemorySize, SMEM_GEMM);
        cudaFuncSetAttribute(fused_attn_kernel, cudaFuncAttributeMaxDynamicSharedMemorySize, SMEM_FA);
        cudaStreamCreateWithFlags(&s2, cudaStreamNonBlocking);
        cudaEventCreateWithFlags(&ev_fork, cudaEventDisableTiming);
        cudaEventCreateWithFlags(&ev_join, cudaEventDisableTiming);
        init_done = 1;
    }

    proj_qkv_kernel<<<dim3(HH / 128, M_PROJ / 128, 3), 256, SMEM_GEMM>>>(q, k, v, Wq, bq, Wk, bk, Wv, bv);
    fused_attn_kernel<<<dim3(SS / QROWS, BH, 2), 256, SMEM_FA>>>(mask, attn);

    // fork: attn_scale on s2, concurrent with combine+out_proj on default
    cudaEventRecord(ev_fork, 0);
    cudaStreamWaitEvent(s2, ev_fork, 0);
    attn_scale_kernel<<<BH * SS, 256, 0, s2>>>(attn);
    cudaEventRecord(ev_join, s2);

    combine_ctx_kernel<<<BB * SS, 192>>>();
    out_proj_kernel<<<dim3(HH / 64, M_PROJ / 128, 1), 256>>>(Wm, bm, out);

    // join: default stream waits for attn_scale before returning
    cudaStreamWaitEvent(0, ev_join, 0);
}

// round 12
// speedup vs baseline: 1.0517x; 1.0517x over previous
#include <cuda_runtime.h>
#include <mma.h>
using namespace nvcuda;

#define BB 2
#define SS 2048
#define HH 768
#define NH 12
#define DD 64
#define BH (BB*NH)
#define M_PROJ (BB*SS)
#define OUT_ELEMS (BB*SS*HH)
#define ATTN_ELEMS ((size_t)BB*NH*SS*SS)

__device__ float g_qh[BB*NH*SS*DD];
__device__ float g_kh[BB*NH*SS*DD];
__device__ float g_vh[BB*NH*SS*DD];
__device__ float g_ctx[BB*SS*HH];
__device__ float g_cpart[2][BB*SS*HH];   // unnormalized partial AV per K-half
__device__ float g_lpart[2][BH*SS];      // partial exp-sums per K-half
__device__ float g_attn_scratch[BB*NH*SS*SS];

typedef wmma::fragment<wmma::matrix_a, 16, 16, 8, wmma::precision::tf32, wmma::row_major> FragA;
typedef wmma::fragment<wmma::matrix_b, 16, 16, 8, wmma::precision::tf32, wmma::col_major> FragBc;
typedef wmma::fragment<wmma::matrix_b, 16, 16, 8, wmma::precision::tf32, wmma::row_major> FragBr;
typedef wmma::fragment<wmma::accumulator, 16, 16, 8, float> FragC;

#define LDS 36           // 32-k slab + 4 pad (proj kernel)
#define SLABK 32
#define NSLAB (HH/SLABK) // 24
#define LDP 68           // 64 + 4
#define LDQ 132          // 128 + 4
#define LDT 20           // 16-k slab + 4 pad (out_proj kernel)
#define KHALF 1024       // K columns per attention CTA

// log2-domain softmax: p = 2^(s * 0.125*log2(e) + b2); masked b2 = -100
#define SC_L2E 0.18033688011112042f
#define MASK_B2 (-100.0f)

#define CVT4(t4) do { \
    t4.x = wmma::__float_to_tf32(t4.x); t4.y = wmma::__float_to_tf32(t4.y); \
    t4.z = wmma::__float_to_tf32(t4.z); t4.w = wmma::__float_to_tf32(t4.w); } while(0)

__device__ __forceinline__ float exp2_mufu(float y) {
    float r;
    asm("ex2.approx.f32 %0, %1;" : "=f"(r) : "f"(y));
    return r;
}

// ============================================================
// Kernel 1: fused QKV projections (128x128 tile, 32-k slab).
// ============================================================
__global__ void __launch_bounds__(256, 2)
proj_qkv_kernel(const float* __restrict__ q,
                const float* __restrict__ k,
                const float* __restrict__ v,
                const float* __restrict__ Wq, const float* __restrict__ bq,
                const float* __restrict__ Wk, const float* __restrict__ bk,
                const float* __restrict__ Wv, const float* __restrict__ bv) {
    const float* X; const float* W; const float* bias; float* Y;
    if (blockIdx.z == 0)      { X = q; W = Wq; bias = bq; Y = g_qh; }
    else if (blockIdx.z == 1) { X = k; W = Wk; bias = bk; Y = g_kh; }
    else                      { X = v; W = Wv; bias = bv; Y = g_vh; }

    extern __shared__ float sm[];
    float* As = sm;
    float* Bs = sm + 128 * LDS;
    float* Cs = sm;
    __shared__ float bias_s[128];

    const int tid = threadIdx.x;
    const int w = tid >> 5;
    const int m0 = blockIdx.y * 128, n0 = blockIdx.x * 128;
    const int wm = (w & 1) * 64, wn = (w >> 1) * 32;
    if (tid < 128) bias_s[tid] = bias[n0 + tid];

    FragC acc[4][2];
    #pragma unroll
    for (int i = 0; i < 4; i++)
        #pragma unroll
        for (int j = 0; j < 2; j++) wmma::fill_fragment(acc[i][j], 0.0f);

    const int r = tid >> 1;
    const int c0 = (tid & 1) * 16;
    const float* xp = X + (size_t)(m0 + r) * HH + c0;
    const float* wp = W + (size_t)(n0 + r) * HH + c0;

    for (int s = 0; s < NSLAB; s++) {
        #pragma unroll
        for (int i = 0; i < 4; i++) {
            float4 t4 = *(const float4*)(xp + s * SLABK + i * 4);
            CVT4(t4); *(float4*)&As[r * LDS + c0 + i * 4] = t4;
            float4 u4 = *(const float4*)(wp + s * SLABK + i * 4);
            CVT4(u4); *(float4*)&Bs[r * LDS + c0 + i * 4] = u4;
        }
        __syncthreads();
        #pragma unroll
        for (int kk = 0; kk < 4; kk++) {
            FragA a[4]; FragBc b[2];
            #pragma unroll
            for (int i = 0; i < 4; i++) wmma::load_matrix_sync(a[i], &As[(wm + i * 16) * LDS + kk * 8], LDS);
            #pragma unroll
            for (int j = 0; j < 2; j++) wmma::load_matrix_sync(b[j], &Bs[(wn + j * 16) * LDS + kk * 8], LDS);
            #pragma unroll
            for (int i = 0; i < 4; i++)
                #pragma unroll
                for (int j = 0; j < 2; j++) wmma::mma_sync(acc[i][j], a[i], b[j], acc[i][j]);
        }
        __syncthreads();
    }

    #pragma unroll
    for (int i = 0; i < 4; i++)
        #pragma unroll
        for (int j = 0; j < 2; j++)
            wmma::store_matrix_sync(&Cs[(wm + i * 16) * LDQ + wn + j * 16], acc[i][j], LDQ, wmma::mem_row_major);
    __syncthreads();

    {
        const int rr = tid >> 1;
        const int cc = (tid & 1) * 64;
        const int h = (n0 + cc) >> 6;
        const int m = m0 + rr, b = m >> 11, s = m & 2047;
        float* dst = &Y[(((size_t)b * NH + h) * SS + s) * DD];
        #pragma unroll
        for (int t = 0; t < 16; t++) {
            float4 t4 = *(float4*)&Cs[rr * LDQ + cc + t * 4];
            t4.x += bias_s[cc + t * 4];     t4.y += bias_s[cc + t * 4 + 1];
            t4.z += bias_s[cc + t * 4 + 2]; t4.w += bias_s[cc + t * 4 + 3];
            *(float4*)&dst[t * 4] = t4;
        }
    }
}

// ============================================================
// Kernel 2: fused attention, K-split 2-way, 128-row Q tiles,
// 2 CTA/SM (R10 config) + register prefetch of next K/V chunk
// issued before the AV phase to hide L2 latency.
// ============================================================
__global__ void __launch_bounds__(256, 2)
fused_attn_kernel(const int* __restrict__ mask, float* __restrict__ attn) {
    extern __shared__ float sm[];
    float* Qs    = sm;                    // [128][LDP]
    float* Ks    = Qs + 128 * LDP;        // [64][LDP]
    float* Vs    = Ks + 64 * LDP;         // [64][LDP]
    float* ps    = Vs + 64 * LDP;         // [128][LDP]
    float* biasv = ps + 128 * LDP;        // [KHALF]

    const int tid = threadIdx.x;
    const int w = tid >> 5;
    const int bh = blockIdx.y;
    const int b = bh / NH, h = bh % NH;
    const int m0 = blockIdx.x * 128;
    const int half = blockIdx.z;
    const int kbase = half * KHALF;
    const int wm = (w >> 1) * 32, wn = (w & 1) * 32;

    const float* qh_head = g_qh + (size_t)bh * SS * DD + (size_t)m0 * DD;
    const float* kh_head = g_kh + (size_t)bh * SS * DD;
    const float* vh_head = g_vh + (size_t)bh * SS * DD;

    #pragma unroll
    for (int jj = 0; jj < 2; jj++) {
        int e = tid + 256 * jj;
        int r = e >> 2, cc = (e & 3) * 16;
        #pragma unroll
        for (int i = 0; i < 4; i++) {
            float4 t4 = *(const float4*)&qh_head[(size_t)r * DD + cc + i * 4];
            CVT4(t4);
            *(float4*)&Qs[r * LDP + cc + i * 4] = t4;
        }
    }
    #pragma unroll
    for (int i = 0; i < 4; i++) {
        int c = tid + 256 * i;
        biasv[c] = mask[b * SS + kbase + c] ? MASK_B2 : 0.0f;
    }

    const int erow = tid >> 1;
    const int cb   = (tid & 1) * 4;   // interleaved: lane pairs cover 32B together
    const int kvr  = tid >> 2, kvc = (tid & 3) * 16;   // K/V load mapping
    float l_run = 0.0f;

    FragC accv[2][2];
    #pragma unroll
    for (int i = 0; i < 2; i++)
        #pragma unroll
        for (int j = 0; j < 2; j++) wmma::fill_fragment(accv[i][j], 0.0f);

    float* arow = attn + ((size_t)bh * SS + m0 + erow) * SS + kbase;

    // prefetch chunk 0 K/V into registers
    float4 kpre[4], vpre[4];
    {
        const float* ksrc = kh_head + (size_t)(kbase + kvr) * DD + kvc;
        const float* vsrc = vh_head + (size_t)(kbase + kvr) * DD + kvc;
        #pragma unroll
        for (int i = 0; i < 4; i++) {
            kpre[i] = *(const float4*)(ksrc + i * 4);
            vpre[i] = *(const float4*)(vsrc + i * 4);
        }
    }
    __syncthreads();   // also covers Qs/biasv init

    for (int cl = 0; cl < KHALF; cl += 64) {
        // ---- store prefetched K/V regs to smem (tf32) ----
        #pragma unroll
        for (int i = 0; i < 4; i++) {
            float4 t4 = kpre[i];
            CVT4(t4); *(float4*)&Ks[kvr * LDP + kvc + i * 4] = t4;
            float4 u4 = vpre[i];
            CVT4(u4); *(float4*)&Vs[kvr * LDP + kvc + i * 4] = u4;
        }
        __syncthreads();

        // ---- S = Q @ K^T (128x64 chunk) ----
        {
            FragC sa[2][2];
            #pragma unroll
            for (int i = 0; i < 2; i++)
                #pragma unroll
                for (int j = 0; j < 2; j++) wmma::fill_fragment(sa[i][j], 0.0f);
            #pragma unroll
            for (int kk = 0; kk < 8; kk++) {
                FragA a0, a1; FragBc b0, b1;
                wmma::load_matrix_sync(a0, &Qs[(wm +  0) * LDP + kk * 8], LDP);
                wmma::load_matrix_sync(a1, &Qs[(wm + 16) * LDP + kk * 8], LDP);
                wmma::load_matrix_sync(b0, &Ks[(wn +  0) * LDP + kk * 8], LDP);
                wmma::load_matrix_sync(b1, &Ks[(wn + 16) * LDP + kk * 8], LDP);
                wmma::mma_sync(sa[0][0], a0, b0, sa[0][0]);
                wmma::mma_sync(sa[0][1], a0, b1, sa[0][1]);
                wmma::mma_sync(sa[1][0], a1, b0, sa[1][0]);
                wmma::mma_sync(sa[1][1], a1, b1, sa[1][1]);
            }
            #pragma unroll
            for (int i = 0; i < 2; i++)
                #pragma unroll
                for (int j = 0; j < 2; j++)
                    wmma::store_matrix_sync(&ps[(wm + i * 16) * LDP + wn + j * 16], sa[i][j], LDP, wmma::mem_row_major);
        }
        __syncthreads();

        // ---- p = 2^(s*SC_L2E + b2); write unnormalized attn ----
        {
            float lsum = 0.0f;
            #pragma unroll
            for (int i = 0; i < 8; i++) {
                int c = cb + i * 8;
                float4 t4 = *(float4*)&ps[erow * LDP + c];
                float4 b4 = *(const float4*)&biasv[cl + c];
                float4 p4;
                p4.x = exp2_mufu(fmaf(t4.x, SC_L2E, b4.x));
                p4.y = exp2_mufu(fmaf(t4.y, SC_L2E, b4.y));
                p4.z = exp2_mufu(fmaf(t4.z, SC_L2E, b4.z));
                p4.w = exp2_mufu(fmaf(t4.w, SC_L2E, b4.w));
                lsum += p4.x + p4.y + p4.z + p4.w;
                *(float4*)&arow[cl + c] = p4;   // unnormalized attn (coalesced pairs)
                CVT4(p4);
                *(float4*)&ps[erow * LDP + c] = p4;
            }
            l_run += lsum;
        }
        __syncthreads();

        // ---- issue prefetch for next chunk (overlaps AV MMAs) ----
        if (cl + 64 < KHALF) {
            const int cn = kbase + cl + 64;
            const float* ksrc = kh_head + (size_t)(cn + kvr) * DD + kvc;
            const float* vsrc = vh_head + (size_t)(cn + kvr) * DD + kvc;
            #pragma unroll
            for (int i = 0; i < 4; i++) {
                kpre[i] = *(const float4*)(ksrc + i * 4);
                vpre[i] = *(const float4*)(vsrc + i * 4);
            }
        }

        // ---- AV accumulate: accv += P(128x64) @ V(64x64) ----
        #pragma unroll
        for (int kk = 0; kk < 8; kk++) {
            FragA a0, a1; FragBr b0, b1;
            wmma::load_matrix_sync(a0, &ps[(wm +  0) * LDP + kk * 8], LDP);
            wmma::load_matrix_sync(a1, &ps[(wm + 16) * LDP + kk * 8], LDP);
            wmma::load_matrix_sync(b0, &Vs[(kk * 8) * LDP + wn +  0], LDP);
            wmma::load_matrix_sync(b1, &Vs[(kk * 8) * LDP + wn + 16], LDP);
            wmma::mma_sync(accv[0][0], a0, b0, accv[0][0]);
            wmma::mma_sync(accv[0][1], a0, b1, accv[0][1]);
            wmma::mma_sync(accv[1][0], a1, b0, accv[1][0]);
            wmma::mma_sync(accv[1][1], a1, b1, accv[1][1]);
        }
        __syncthreads();
    }

    l_run += __shfl_xor_sync(0xFFFFFFFFu, l_run, 1);
    if ((tid & 1) == 0) g_lpart[half][bh * SS + m0 + erow] = l_run;

    #pragma unroll
    for (int i = 0; i < 2; i++)
        #pragma unroll
        for (int j = 0; j < 2; j++)
            wmma::store_matrix_sync(&ps[(wm + i * 16) * LDP + wn + j * 16], accv[i][j], LDP, wmma::mem_row_major);
    __syncthreads();
    {
        float* dst = &g_cpart[half][((size_t)(b * SS + m0 + erow)) * HH + h * 64];
        #pragma unroll
        for (int i = 0; i < 8; i++) {
            int c = cb + i * 8;
            float4 t4 = *(float4*)&ps[erow * LDP + c];
            *(float4*)&dst[c] = t4;   // unnormalized partial, coalesced pairs
        }
    }
}

// ============================================================
// Kernel 3: combine partial AV halves: ctx = (P0+P1)/(l0+l1).
// ============================================================
__global__ void __launch_bounds__(192)
combine_ctx_kernel() {
    const int row = blockIdx.x;           // b*SS + s
    const int b = row >> 11, s = row & 2047;
    __shared__ float inv_s[NH];
    if (threadIdx.x < NH) {
        int li = (b * NH + threadIdx.x) * SS + s;
        inv_s[threadIdx.x] = 1.0f / (g_lpart[0][li] + g_lpart[1][li]);
    }
    __syncthreads();
    const int n = threadIdx.x * 4;
    const float inv = inv_s[n >> 6];
    const size_t base = (size_t)row * HH + n;
    float4 a = *(const float4*)&g_cpart[0][base];
    float4 c = *(const float4*)&g_cpart[1][base];
    a.x = (a.x + c.x) * inv; a.y = (a.y + c.y) * inv;
    a.z = (a.z + c.z) * inv; a.w = (a.w + c.w) * inv;
    *(float4*)&g_ctx[base] = a;
}

// ============================================================
// Kernel 4: attn rescale (block per row, coalesced streaming).
// ============================================================
__global__ void __launch_bounds__(256)
attn_scale_kernel(float* __restrict__ attn) {
    const int row = blockIdx.x;
    const float inv = 1.0f / (g_lpart[0][row] + g_lpart[1][row]);
    float* p = attn + (size_t)row * SS;
    const int t = threadIdx.x;
    #pragma unroll
    for (int i = 0; i < 2; i++) {
        int c = (t + i * 256) * 4;
        float4 v4 = *(float4*)&p[c];
        v4.x *= inv; v4.y *= inv; v4.z *= inv; v4.w *= inv;
        *(float4*)&p[c] = v4;
    }
}

// ============================================================
// Kernel 5: out = ctx @ Wm^T + bm (128x64 tile, 16-k slab).
// ============================================================
__global__ void __launch_bounds__(256)
out_proj_kernel(const float* __restrict__ Wm,
                const float* __restrict__ bm,
                float* __restrict__ out) {
    __shared__ float sbuf[128 * LDP];
    __shared__ float bias_s[64];
    float* As = sbuf;
    float* Bs = sbuf + 128 * LDT;
    float* Cs = sbuf;

    const int tid = threadIdx.x;
    const int w = tid >> 5;
    const int m0 = blockIdx.y * 128, n0 = blockIdx.x * 64;
    const int mw = (w >> 1) * 32, nw = (w & 1) * 32;
    if (tid < 64) bias_s[tid] = bm[n0 + tid];

    FragC acc[2][2];
    #pragma unroll
    for (int i = 0; i < 2; i++)
        #pragma unroll
        for (int j = 0; j < 2; j++) wmma::fill_fragment(acc[i][j], 0.0f);

    for (int k0 = 0; k0 < HH; k0 += 16) {
        #pragma unroll
        for (int jj = 0; jj < 2; jj++) {
            int e = tid + 256 * jj;
            int r = e >> 2, c4 = (e & 3) * 4;
            float4 t4 = *(const float4*)&g_ctx[(size_t)(m0 + r) * HH + k0 + c4];
            CVT4(t4);
            *(float4*)&As[r * LDT + c4] = t4;
        }
        {
            int r = tid >> 2, c4 = (tid & 3) * 4;
            float4 t4 = *(const float4*)&Wm[(size_t)(n0 + r) * HH + k0 + c4];
            CVT4(t4);
            *(float4*)&Bs[r * LDT + c4] = t4;
        }
        __syncthreads();
        #pragma unroll
        for (int kt = 0; kt < 2; kt++) {
            FragA a0, a1; FragBc b0, b1;
            wmma::load_matrix_sync(a0, &As[(mw +  0) * LDT + kt * 8], LDT);
            wmma::load_matrix_sync(a1, &As[(mw + 16) * LDT + kt * 8], LDT);
            wmma::load_matrix_sync(b0, &Bs[(nw +  0) * LDT + kt * 8], LDT);
            wmma::load_matrix_sync(b1, &Bs[(nw + 16) * LDT + kt * 8], LDT);
            wmma::mma_sync(acc[0][0], a0, b0, acc[0][0]);
            wmma::mma_sync(acc[0][1], a0, b1, acc[0][1]);
            wmma::mma_sync(acc[1][0], a1, b0, acc[1][0]);
            wmma::mma_sync(acc[1][1], a1, b1, acc[1][1]);
        }
        __syncthreads();
    }
    #pragma unroll
    for (int i = 0; i < 2; i++)
        #pragma unroll
        for (int j = 0; j < 2; j++)
            wmma::store_matrix_sync(&Cs[(mw + i * 16) * LDP + nw + j * 16], acc[i][j], LDP, wmma::mem_row_major);
    __syncthreads();

    #pragma unroll
    for (int jj = 0; jj < 8; jj++) {
        int e = tid + 256 * jj;
        int r = e >> 4, c4 = (e & 15) * 4;
        float4 t4 = *(float4*)&Cs[r * LDP + c4];
        t4.x += bias_s[c4]; t4.y += bias_s[c4 + 1];
        t4.z += bias_s[c4 + 2]; t4.w += bias_s[c4 + 3];
        *(float4*)&out[(size_t)(m0 + r) * HH + n0 + c4] = t4;
    }
}

// ============================================================
// Host launcher — attn_scale overlapped with combine+out_proj.
// ============================================================
extern "C" void kernel_launch(void* const* d_in, const int* in_sizes, int n_in,
                              void* d_out, int out_size) {
    const float* v    = (const float*)d_in[0];
    const float* k    = (const float*)d_in[1];
    const float* q    = (const float*)d_in[2];
    const int*   mask = (const int*)  d_in[3];
    const float* Wv   = (const float*)d_in[4];
    const float* bv   = (const float*)d_in[5];
    const float* Wk   = (const float*)d_in[6];
    const float* bk   = (const float*)d_in[7];
    const float* Wq   = (const float*)d_in[8];
    const float* bq   = (const float*)d_in[9];
    const float* Wm   = (const float*)d_in[10];
    const float* bm   = (const float*)d_in[11];
    float* out = (float*)d_out;

    float* attn;
    if ((size_t)out_size >= (size_t)OUT_ELEMS + ATTN_ELEMS) {
        attn = out + OUT_ELEMS;
    } else {
        void* p = nullptr;
        cudaGetSymbolAddress(&p, g_attn_scratch);
        attn = (float*)p;
    }

    const int SMEM_GEMM = 128 * LDQ * 4;                                             // 67584
    const int SMEM_FA   = (128 * LDP + 64 * LDP + 64 * LDP + 128 * LDP + KHALF) * 4; // 108544
    static int init_done = 0;
    static cudaStream_t s2;
    static cudaEvent_t ev_fork, ev_join;
    if (!init_done) {
        cudaFuncSetAttribute(proj_qkv_kernel, cudaFuncAttributeMaxDynamicSharedMemorySize, SMEM_GEMM);
        cudaFuncSetAttribute(fused_attn_kernel, cudaFuncAttributeMaxDynamicSharedMemorySize, SMEM_FA);
        cudaStreamCreateWithFlags(&s2, cudaStreamNonBlocking);
        cudaEventCreateWithFlags(&ev_fork, cudaEventDisableTiming);
        cudaEventCreateWithFlags(&ev_join, cudaEventDisableTiming);
        init_done = 1;
    }

    proj_qkv_kernel<<<dim3(HH / 128, M_PROJ / 128, 3), 256, SMEM_GEMM>>>(q, k, v, Wq, bq, Wk, bk, Wv, bv);
    fused_attn_kernel<<<dim3(SS / 128, BH, 2), 256, SMEM_FA>>>(mask, attn);

    // fork: attn_scale on s2, concurrent with combine+out_proj on default
    cudaEventRecord(ev_fork, 0);
    cudaStreamWaitEvent(s2, ev_fork, 0);
    attn_scale_kernel<<<BH * SS, 256, 0, s2>>>(attn);
    cudaEventRecord(ev_join, s2);

    combine_ctx_kernel<<<BB * SS, 192>>>();
    out_proj_kernel<<<dim3(HH / 64, M_PROJ / 128, 1), 256>>>(Wm, bm, out);

    // join: default stream waits for attn_scale before returning
    cudaStreamWaitEvent(0, ev_join, 0);
}

// round 13
// speedup vs baseline: 1.0622x; 1.0100x over previous
#include <cuda_runtime.h>
#include <mma.h>
using namespace nvcuda;

#define BB 2
#define SS 2048
#define HH 768
#define NH 12
#define DD 64
#define BH (BB*NH)
#define M_PROJ (BB*SS)
#define OUT_ELEMS (BB*SS*HH)
#define ATTN_ELEMS ((size_t)BB*NH*SS*SS)

__device__ float g_qh[BB*NH*SS*DD];
__device__ float g_kh[BB*NH*SS*DD];
__device__ float g_vh[BB*NH*SS*DD];
__device__ float g_ctx[BB*SS*HH];
__device__ float g_cpart[2][BB*SS*HH];   // unnormalized partial AV per K-half
__device__ float g_lpart[2][BH*SS];      // partial exp-sums per K-half
__device__ float g_attn_scratch[BB*NH*SS*SS];

typedef wmma::fragment<wmma::matrix_a, 16, 16, 8, wmma::precision::tf32, wmma::row_major> FragA;
typedef wmma::fragment<wmma::matrix_b, 16, 16, 8, wmma::precision::tf32, wmma::col_major> FragBc;
typedef wmma::fragment<wmma::matrix_b, 16, 16, 8, wmma::precision::tf32, wmma::row_major> FragBr;
typedef wmma::fragment<wmma::accumulator, 16, 16, 8, float> FragC;

#define LDS 36           // 32-k slab + 4 pad (proj kernel)
#define SLABK 32
#define NSLAB (HH/SLABK) // 24
#define LDP 68           // 64 + 4
#define LDQ 132          // 128 + 4
#define LDT 20           // 16-k slab + 4 pad (out_proj kernel)
#define KHALF 1024       // K columns per attention CTA

// log2-domain softmax: p = 2^(s * 0.125*log2(e) + b2); masked b2 = -100
#define SC_L2E 0.18033688011112042f
#define MASK_B2 (-100.0f)

#define CVT4(t4) do { \
    t4.x = wmma::__float_to_tf32(t4.x); t4.y = wmma::__float_to_tf32(t4.y); \
    t4.z = wmma::__float_to_tf32(t4.z); t4.w = wmma::__float_to_tf32(t4.w); } while(0)

__device__ __forceinline__ float exp2_mufu(float y) {
    float r;
    asm("ex2.approx.f32 %0, %1;" : "=f"(r) : "f"(y));
    return r;
}

// ============================================================
// Kernel 1: fused QKV projections (128x128 tile, 32-k slab).
// ============================================================
__global__ void __launch_bounds__(256, 2)
proj_qkv_kernel(const float* __restrict__ q,
                const float* __restrict__ k,
                const float* __restrict__ v,
                const float* __restrict__ Wq, const float* __restrict__ bq,
                const float* __restrict__ Wk, const float* __restrict__ bk,
                const float* __restrict__ Wv, const float* __restrict__ bv) {
    const float* X; const float* W; const float* bias; float* Y;
    if (blockIdx.z == 0)      { X = q; W = Wq; bias = bq; Y = g_qh; }
    else if (blockIdx.z == 1) { X = k; W = Wk; bias = bk; Y = g_kh; }
    else                      { X = v; W = Wv; bias = bv; Y = g_vh; }

    extern __shared__ float sm[];
    float* As = sm;
    float* Bs = sm + 128 * LDS;
    float* Cs = sm;
    __shared__ float bias_s[128];

    const int tid = threadIdx.x;
    const int w = tid >> 5;
    const int m0 = blockIdx.y * 128, n0 = blockIdx.x * 128;
    const int wm = (w & 1) * 64, wn = (w >> 1) * 32;
    if (tid < 128) bias_s[tid] = bias[n0 + tid];

    FragC acc[4][2];
    #pragma unroll
    for (int i = 0; i < 4; i++)
        #pragma unroll
        for (int j = 0; j < 2; j++) wmma::fill_fragment(acc[i][j], 0.0f);

    const int r = tid >> 1;
    const int c0 = (tid & 1) * 16;
    const float* xp = X + (size_t)(m0 + r) * HH + c0;
    const float* wp = W + (size_t)(n0 + r) * HH + c0;

    for (int s = 0; s < NSLAB; s++) {
        #pragma unroll
        for (int i = 0; i < 4; i++) {
            float4 t4 = *(const float4*)(xp + s * SLABK + i * 4);
            CVT4(t4); *(float4*)&As[r * LDS + c0 + i * 4] = t4;
            float4 u4 = *(const float4*)(wp + s * SLABK + i * 4);
            CVT4(u4); *(float4*)&Bs[r * LDS + c0 + i * 4] = u4;
        }
        __syncthreads();
        #pragma unroll
        for (int kk = 0; kk < 4; kk++) {
            FragA a[4]; FragBc b[2];
            #pragma unroll
            for (int i = 0; i < 4; i++) wmma::load_matrix_sync(a[i], &As[(wm + i * 16) * LDS + kk * 8], LDS);
            #pragma unroll
            for (int j = 0; j < 2; j++) wmma::load_matrix_sync(b[j], &Bs[(wn + j * 16) * LDS + kk * 8], LDS);
            #pragma unroll
            for (int i = 0; i < 4; i++)
                #pragma unroll
                for (int j = 0; j < 2; j++) wmma::mma_sync(acc[i][j], a[i], b[j], acc[i][j]);
        }
        __syncthreads();
    }

    #pragma unroll
    for (int i = 0; i < 4; i++)
        #pragma unroll
        for (int j = 0; j < 2; j++)
            wmma::store_matrix_sync(&Cs[(wm + i * 16) * LDQ + wn + j * 16], acc[i][j], LDQ, wmma::mem_row_major);
    __syncthreads();

    {
        const int rr = tid >> 1;
        const int cc = (tid & 1) * 64;
        const int h = (n0 + cc) >> 6;
        const int m = m0 + rr, b = m >> 11, s = m & 2047;
        float* dst = &Y[(((size_t)b * NH + h) * SS + s) * DD];
        #pragma unroll
        for (int t = 0; t < 16; t++) {
            float4 t4 = *(float4*)&Cs[rr * LDQ + cc + t * 4];
            t4.x += bias_s[cc + t * 4];     t4.y += bias_s[cc + t * 4 + 1];
            t4.z += bias_s[cc + t * 4 + 2]; t4.w += bias_s[cc + t * 4 + 3];
            *(float4*)&dst[t * 4] = t4;
        }
    }
}

// ============================================================
// Kernel 2: fused attention, K-split 2-way, 128-row Q tiles,
// 2 CTA/SM, register prefetch + WARP-LOCAL exp phase
// (3 barriers per chunk instead of 4).
// ============================================================
__global__ void __launch_bounds__(256, 2)
fused_attn_kernel(const int* __restrict__ mask, float* __restrict__ attn) {
    extern __shared__ float sm[];
    float* Qs    = sm;                    // [128][LDP]
    float* Ks    = Qs + 128 * LDP;        // [64][LDP]
    float* Vs    = Ks + 64 * LDP;         // [64][LDP]
    float* ps    = Vs + 64 * LDP;         // [128][LDP]
    float* biasv = ps + 128 * LDP;        // [KHALF]
    float* lsmem = biasv + KHALF;         // [128][2]

    const int tid = threadIdx.x;
    const int w = tid >> 5;
    const int lane = tid & 31;
    const int bh = blockIdx.y;
    const int b = bh / NH, h = bh % NH;
    const int m0 = blockIdx.x * 128;
    const int half = blockIdx.z;
    const int kbase = half * KHALF;
    const int wm = (w >> 1) * 32, wn = (w & 1) * 32;

    const float* qh_head = g_qh + (size_t)bh * SS * DD + (size_t)m0 * DD;
    const float* kh_head = g_kh + (size_t)bh * SS * DD;
    const float* vh_head = g_vh + (size_t)bh * SS * DD;

    #pragma unroll
    for (int jj = 0; jj < 2; jj++) {
        int e = tid + 256 * jj;
        int r = e >> 2, cc = (e & 3) * 16;
        #pragma unroll
        for (int i = 0; i < 4; i++) {
            float4 t4 = *(const float4*)&qh_head[(size_t)r * DD + cc + i * 4];
            CVT4(t4);
            *(float4*)&Qs[r * LDP + cc + i * 4] = t4;
        }
    }
    #pragma unroll
    for (int i = 0; i < 4; i++) {
        int c = tid + 256 * i;
        biasv[c] = mask[b * SS + kbase + c] ? MASK_B2 : 0.0f;
    }

    // warp-local exp mapping: rows wm+r2 / wm+16+r2, cols wn + hl*4 + i*8
    const int r2 = lane >> 1;
    const int hl = lane & 1;
    const int rowA = wm + r2, rowB = wm + 16 + r2;
    float* arowA = attn + ((size_t)bh * SS + m0 + rowA) * SS + kbase;
    float* arowB = attn + ((size_t)bh * SS + m0 + rowB) * SS + kbase;
    float lsumA = 0.0f, lsumB = 0.0f;

    const int kvr = tid >> 2, kvc = (tid & 3) * 16;   // K/V load mapping

    FragC accv[2][2];
    #pragma unroll
    for (int i = 0; i < 2; i++)
        #pragma unroll
        for (int j = 0; j < 2; j++) wmma::fill_fragment(accv[i][j], 0.0f);

    // prefetch chunk 0 K/V into registers
    float4 kpre[4], vpre[4];
    {
        const float* ksrc = kh_head + (size_t)(kbase + kvr) * DD + kvc;
        const float* vsrc = vh_head + (size_t)(kbase + kvr) * DD + kvc;
        #pragma unroll
        for (int i = 0; i < 4; i++) {
            kpre[i] = *(const float4*)(ksrc + i * 4);
            vpre[i] = *(const float4*)(vsrc + i * 4);
        }
    }
    __syncthreads();   // also covers Qs/biasv init

    for (int cl = 0; cl < KHALF; cl += 64) {
        // ---- store prefetched K/V regs to smem (tf32) ----
        #pragma unroll
        for (int i = 0; i < 4; i++) {
            float4 t4 = kpre[i];
            CVT4(t4); *(float4*)&Ks[kvr * LDP + kvc + i * 4] = t4;
            float4 u4 = vpre[i];
            CVT4(u4); *(float4*)&Vs[kvr * LDP + kvc + i * 4] = u4;
        }
        __syncthreads();                                    // B1

        // ---- S = Q @ K^T (warp subtile 32x32) ----
        {
            FragC sa[2][2];
            #pragma unroll
            for (int i = 0; i < 2; i++)
                #pragma unroll
                for (int j = 0; j < 2; j++) wmma::fill_fragment(sa[i][j], 0.0f);
            #pragma unroll
            for (int kk = 0; kk < 8; kk++) {
                FragA a0, a1; FragBc b0, b1;
                wmma::load_matrix_sync(a0, &Qs[(wm +  0) * LDP + kk * 8], LDP);
                wmma::load_matrix_sync(a1, &Qs[(wm + 16) * LDP + kk * 8], LDP);
                wmma::load_matrix_sync(b0, &Ks[(wn +  0) * LDP + kk * 8], LDP);
                wmma::load_matrix_sync(b1, &Ks[(wn + 16) * LDP + kk * 8], LDP);
                wmma::mma_sync(sa[0][0], a0, b0, sa[0][0]);
                wmma::mma_sync(sa[0][1], a0, b1, sa[0][1]);
                wmma::mma_sync(sa[1][0], a1, b0, sa[1][0]);
                wmma::mma_sync(sa[1][1], a1, b1, sa[1][1]);
            }
            #pragma unroll
            for (int i = 0; i < 2; i++)
                #pragma unroll
                for (int j = 0; j < 2; j++)
                    wmma::store_matrix_sync(&ps[(wm + i * 16) * LDP + wn + j * 16], sa[i][j], LDP, wmma::mem_row_major);
        }

        // ---- WARP-LOCAL exp on own 32x32 subtile (no CTA barrier) ----
        {
            #pragma unroll
            for (int i = 0; i < 4; i++) {
                int c = wn + hl * 4 + i * 8;
                float4 bA = *(const float4*)&biasv[cl + c];
                float4 tA = *(float4*)&ps[rowA * LDP + c];
                float4 pA;
                pA.x = exp2_mufu(fmaf(tA.x, SC_L2E, bA.x));
                pA.y = exp2_mufu(fmaf(tA.y, SC_L2E, bA.y));
                pA.z = exp2_mufu(fmaf(tA.z, SC_L2E, bA.z));
                pA.w = exp2_mufu(fmaf(tA.w, SC_L2E, bA.w));
                lsumA += pA.x + pA.y + pA.z + pA.w;
                *(float4*)&arowA[cl + c] = pA;
                CVT4(pA);
                *(float4*)&ps[rowA * LDP + c] = pA;

                float4 tB = *(float4*)&ps[rowB * LDP + c];
                float4 pB;
                pB.x = exp2_mufu(fmaf(tB.x, SC_L2E, bA.x));
                pB.y = exp2_mufu(fmaf(tB.y, SC_L2E, bA.y));
                pB.z = exp2_mufu(fmaf(tB.z, SC_L2E, bA.z));
                pB.w = exp2_mufu(fmaf(tB.w, SC_L2E, bA.w));
                lsumB += pB.x + pB.y + pB.z + pB.w;
                *(float4*)&arowB[cl + c] = pB;
                CVT4(pB);
                *(float4*)&ps[rowB * LDP + c] = pB;
            }
        }
        __syncthreads();                                    // B2 (ps ready for AV)

        // ---- issue prefetch for next chunk (overlaps AV MMAs) ----
        if (cl + 64 < KHALF) {
            const int cn = kbase + cl + 64;
            const float* ksrc = kh_head + (size_t)(cn + kvr) * DD + kvc;
            const float* vsrc = vh_head + (size_t)(cn + kvr) * DD + kvc;
            #pragma unroll
            for (int i = 0; i < 4; i++) {
                kpre[i] = *(const float4*)(ksrc + i * 4);
                vpre[i] = *(const float4*)(vsrc + i * 4);
            }
        }

        // ---- AV accumulate: accv += P(128x64) @ V(64x64) ----
        #pragma unroll
        for (int kk = 0; kk < 8; kk++) {
            FragA a0, a1; FragBr b0, b1;
            wmma::load_matrix_sync(a0, &ps[(wm +  0) * LDP + kk * 8], LDP);
            wmma::load_matrix_sync(a1, &ps[(wm + 16) * LDP + kk * 8], LDP);
            wmma::load_matrix_sync(b0, &Vs[(kk * 8) * LDP + wn +  0], LDP);
            wmma::load_matrix_sync(b1, &Vs[(kk * 8) * LDP + wn + 16], LDP);
            wmma::mma_sync(accv[0][0], a0, b0, accv[0][0]);
            wmma::mma_sync(accv[0][1], a0, b1, accv[0][1]);
            wmma::mma_sync(accv[1][0], a1, b0, accv[1][0]);
            wmma::mma_sync(accv[1][1], a1, b1, accv[1][1]);
        }
        __syncthreads();                                    // B3
    }

    // ---- combine row sums across the 2 col-warps via smem ----
    lsumA += __shfl_xor_sync(0xFFFFFFFFu, lsumA, 1);
    lsumB += __shfl_xor_sync(0xFFFFFFFFu, lsumB, 1);
    if (hl == 0) {
        lsmem[rowA * 2 + (w & 1)] = lsumA;
        lsmem[rowB * 2 + (w & 1)] = lsumB;
    }
    __syncthreads();
    if (tid < 128)
        g_lpart[half][bh * SS + m0 + tid] = lsmem[tid * 2] + lsmem[tid * 2 + 1];

    // ---- store AV accumulators, write unnormalized ctx partial ----
    #pragma unroll
    for (int i = 0; i < 2; i++)
        #pragma unroll
        for (int j = 0; j < 2; j++)
            wmma::store_matrix_sync(&ps[(wm + i * 16) * LDP + wn + j * 16], accv[i][j], LDP, wmma::mem_row_major);
    __syncthreads();
    {
        const int erow = tid >> 1;
        const int cb = (tid & 1) * 4;
        float* dst = &g_cpart[half][((size_t)(b * SS + m0 + erow)) * HH + h * 64];
        #pragma unroll
        for (int i = 0; i < 8; i++) {
            int c = cb + i * 8;
            float4 t4 = *(float4*)&ps[erow * LDP + c];
            *(float4*)&dst[c] = t4;
        }
    }
}

// ============================================================
// Kernel 3: combine partial AV halves: ctx = (P0+P1)/(l0+l1).
// ============================================================
__global__ void __launch_bounds__(192)
combine_ctx_kernel() {
    const int row = blockIdx.x;           // b*SS + s
    const int b = row >> 11, s = row & 2047;
    __shared__ float inv_s[NH];
    if (threadIdx.x < NH) {
        int li = (b * NH + threadIdx.x) * SS + s;
        inv_s[threadIdx.x] = 1.0f / (g_lpart[0][li] + g_lpart[1][li]);
    }
    __syncthreads();
    const int n = threadIdx.x * 4;
    const float inv = inv_s[n >> 6];
    const size_t base = (size_t)row * HH + n;
    float4 a = *(const float4*)&g_cpart[0][base];
    float4 c = *(const float4*)&g_cpart[1][base];
    a.x = (a.x + c.x) * inv; a.y = (a.y + c.y) * inv;
    a.z = (a.z + c.z) * inv; a.w = (a.w + c.w) * inv;
    *(float4*)&g_ctx[base] = a;
}

// ============================================================
// Kernel 4: attn rescale (block per row, coalesced streaming).
// ============================================================
__global__ void __launch_bounds__(256)
attn_scale_kernel(float* __restrict__ attn) {
    const int row = blockIdx.x;
    const float inv = 1.0f / (g_lpart[0][row] + g_lpart[1][row]);
    float* p = attn + (size_t)row * SS;
    const int t = threadIdx.x;
    #pragma unroll
    for (int i = 0; i < 2; i++) {
        int c = (t + i * 256) * 4;
        float4 v4 = *(float4*)&p[c];
        v4.x *= inv; v4.y *= inv; v4.z *= inv; v4.w *= inv;
        *(float4*)&p[c] = v4;
    }
}

// ============================================================
// Kernel 5: out = ctx @ Wm^T + bm (128x64 tile, 16-k slab).
// ============================================================
__global__ void __launch_bounds__(256)
out_proj_kernel(const float* __restrict__ Wm,
                const float* __restrict__ bm,
                float* __restrict__ out) {
    __shared__ float sbuf[128 * LDP];
    __shared__ float bias_s[64];
    float* As = sbuf;
    float* Bs = sbuf + 128 * LDT;
    float* Cs = sbuf;

    const int tid = threadIdx.x;
    const int w = tid >> 5;
    const int m0 = blockIdx.y * 128, n0 = blockIdx.x * 64;
    const int mw = (w >> 1) * 32, nw = (w & 1) * 32;
    if (tid < 64) bias_s[tid] = bm[n0 + tid];

    FragC acc[2][2];
    #pragma unroll
    for (int i = 0; i < 2; i++)
        #pragma unroll
        for (int j = 0; j < 2; j++) wmma::fill_fragment(acc[i][j], 0.0f);

    for (int k0 = 0; k0 < HH; k0 += 16) {
        #pragma unroll
        for (int jj = 0; jj < 2; jj++) {
            int e = tid + 256 * jj;
            int r = e >> 2, c4 = (e & 3) * 4;
            float4 t4 = *(const float4*)&g_ctx[(size_t)(m0 + r) * HH + k0 + c4];
            CVT4(t4);
            *(float4*)&As[r * LDT + c4] = t4;
        }
        {
            int r = tid >> 2, c4 = (tid & 3) * 4;
            float4 t4 = *(const float4*)&Wm[(size_t)(n0 + r) * HH + k0 + c4];
            CVT4(t4);
            *(float4*)&Bs[r * LDT + c4] = t4;
        }
        __syncthreads();
        #pragma unroll
        for (int kt = 0; kt < 2; kt++) {
            FragA a0, a1; FragBc b0, b1;
            wmma::load_matrix_sync(a0, &As[(mw +  0) * LDT + kt * 8], LDT);
            wmma::load_matrix_sync(a1, &As[(mw + 16) * LDT + kt * 8], LDT);
            wmma::load_matrix_sync(b0, &Bs[(nw +  0) * LDT + kt * 8], LDT);
            wmma::load_matrix_sync(b1, &Bs[(nw + 16) * LDT + kt * 8], LDT);
            wmma::mma_sync(acc[0][0], a0, b0, acc[0][0]);
            wmma::mma_sync(acc[0][1], a0, b1, acc[0][1]);
            wmma::mma_sync(acc[1][0], a1, b0, acc[1][0]);
            wmma::mma_sync(acc[1][1], a1, b1, acc[1][1]);
        }
        __syncthreads();
    }
    #pragma unroll
    for (int i = 0; i < 2; i++)
        #pragma unroll
        for (int j = 0; j < 2; j++)
            wmma::store_matrix_sync(&Cs[(mw + i * 16) * LDP + nw + j * 16], acc[i][j], LDP, wmma::mem_row_major);
    __syncthreads();

    #pragma unroll
    for (int jj = 0; jj < 8; jj++) {
        int e = tid + 256 * jj;
        int r = e >> 4, c4 = (e & 15) * 4;
        float4 t4 = *(float4*)&Cs[r * LDP + c4];
        t4.x += bias_s[c4]; t4.y += bias_s[c4 + 1];
        t4.z += bias_s[c4 + 2]; t4.w += bias_s[c4 + 3];
        *(float4*)&out[(size_t)(m0 + r) * HH + n0 + c4] = t4;
    }
}

// ============================================================
// Host launcher — attn_scale overlapped with combine+out_proj.
// ============================================================
extern "C" void kernel_launch(void* const* d_in, const int* in_sizes, int n_in,
                              void* d_out, int out_size) {
    const float* v    = (const float*)d_in[0];
    const float* k    = (const float*)d_in[1];
    const float* q    = (const float*)d_in[2];
    const int*   mask = (const int*)  d_in[3];
    const float* Wv   = (const float*)d_in[4];
    const float* bv   = (const float*)d_in[5];
    const float* Wk   = (const float*)d_in[6];
    const float* bk   = (const float*)d_in[7];
    const float* Wq   = (const float*)d_in[8];
    const float* bq   = (const float*)d_in[9];
    const float* Wm   = (const float*)d_in[10];
    const float* bm   = (const float*)d_in[11];
    float* out = (float*)d_out;

    float* attn;
    if ((size_t)out_size >= (size_t)OUT_ELEMS + ATTN_ELEMS) {
        attn = out + OUT_ELEMS;
    } else {
        void* p = nullptr;
        cudaGetSymbolAddress(&p, g_attn_scratch);
        attn = (float*)p;
    }

    const int SMEM_GEMM = 128 * LDQ * 4;                                                   // 67584
    const int SMEM_FA   = (128 * LDP + 64 * LDP + 64 * LDP + 128 * LDP + KHALF + 256) * 4; // 109568
    static int init_done = 0;
    static cudaStream_t s2;
    static cudaEvent_t ev_fork, ev_join;
    if (!init_done) {
        cudaFuncSetAttribute(proj_qkv_kernel, cudaFuncAttributeMaxDynamicSharedMemorySize, SMEM_GEMM);
        cudaFuncSetAttribute(fused_attn_kernel, cudaFuncAttributeMaxDynamicSharedMemorySize, SMEM_FA);
        cudaStreamCreateWithFlags(&s2, cudaStreamNonBlocking);
        cudaEventCreateWithFlags(&ev_fork, cudaEventDisableTiming);
        cudaEventCreateWithFlags(&ev_join, cudaEventDisableTiming);
        init_done = 1;
    }

    proj_qkv_kernel<<<dim3(HH / 128, M_PROJ / 128, 3), 256, SMEM_GEMM>>>(q, k, v, Wq, bq, Wk, bk, Wv, bv);
    fused_attn_kernel<<<dim3(SS / 128, BH, 2), 256, SMEM_FA>>>(mask, attn);

    // fork: attn_scale on s2, concurrent with combine+out_proj on default
    cudaEventRecord(ev_fork, 0);
    cudaStreamWaitEvent(s2, ev_fork, 0);
    attn_scale_kernel<<<BH * SS, 256, 0, s2>>>(attn);
    cudaEventRecord(ev_join, s2);

    combine_ctx_kernel<<<BB * SS, 192>>>();
    out_proj_kernel<<<dim3(HH / 64, M_PROJ / 128, 1), 256>>>(Wm, bm, out);

    // join: default stream waits for attn_scale before returning
    cudaStreamWaitEvent(0, ev_join, 0);
}

// round 14
// speedup vs baseline: 1.0653x; 1.0029x over previous
#include <cuda_runtime.h>
#include <mma.h>
using namespace nvcuda;

#define BB 2
#define SS 2048
#define HH 768
#define NH 12
#define DD 64
#define BH (BB*NH)
#define M_PROJ (BB*SS)
#define OUT_ELEMS (BB*SS*HH)
#define ATTN_ELEMS ((size_t)BB*NH*SS*SS)

__device__ float g_qh[BB*NH*SS*DD];
__device__ float g_kh[BB*NH*SS*DD];
__device__ float g_vh[BB*NH*SS*DD];
__device__ float g_ctx[BB*SS*HH];
__device__ float g_cpart[2][BB*SS*HH];   // unnormalized partial AV per K-half
__device__ float g_lpart[2][BH*SS];      // partial exp-sums per K-half
__device__ float g_attn_scratch[BB*NH*SS*SS];

typedef wmma::fragment<wmma::matrix_a, 16, 16, 8, wmma::precision::tf32, wmma::row_major> FragA;
typedef wmma::fragment<wmma::matrix_b, 16, 16, 8, wmma::precision::tf32, wmma::col_major> FragBc;
typedef wmma::fragment<wmma::matrix_b, 16, 16, 8, wmma::precision::tf32, wmma::row_major> FragBr;
typedef wmma::fragment<wmma::accumulator, 16, 16, 8, float> FragC;

#define SLABK 64
#define NSLAB (HH/SLABK) // 12
#define LDS 68           // 64-k slab + 4 pad (proj kernel)
#define LDP 68           // 64 + 4
#define LDQ 132          // 128 + 4
#define LDT 20           // 16-k slab + 4 pad (out_proj kernel)
#define KHALF 1024       // K columns per attention CTA

// log2-domain softmax: p = 2^(s * 0.125*log2(e) + b2); masked b2 = -100
#define SC_L2E 0.18033688011112042f
#define MASK_B2 (-100.0f)

#define CVT4(t4) do { \
    t4.x = wmma::__float_to_tf32(t4.x); t4.y = wmma::__float_to_tf32(t4.y); \
    t4.z = wmma::__float_to_tf32(t4.z); t4.w = wmma::__float_to_tf32(t4.w); } while(0)

__device__ __forceinline__ float exp2_mufu(float y) {
    float r;
    asm("ex2.approx.f32 %0, %1;" : "=f"(r) : "f"(y));
    return r;
}

// ============================================================
// Kernel 1: fused QKV projections (128x128 tile, 64-k slab).
// ============================================================
__global__ void __launch_bounds__(256, 2)
proj_qkv_kernel(const float* __restrict__ q,
                const float* __restrict__ k,
                const float* __restrict__ v,
                const float* __restrict__ Wq, const float* __restrict__ bq,
                const float* __restrict__ Wk, const float* __restrict__ bk,
                const float* __restrict__ Wv, const float* __restrict__ bv) {
    const float* X; const float* W; const float* bias; float* Y;
    if (blockIdx.z == 0)      { X = q; W = Wq; bias = bq; Y = g_qh; }
    else if (blockIdx.z == 1) { X = k; W = Wk; bias = bk; Y = g_kh; }
    else                      { X = v; W = Wv; bias = bv; Y = g_vh; }

    extern __shared__ float sm[];
    float* As = sm;
    float* Bs = sm + 128 * LDS;
    float* Cs = sm;
    __shared__ float bias_s[128];

    const int tid = threadIdx.x;
    const int w = tid >> 5;
    const int m0 = blockIdx.y * 128, n0 = blockIdx.x * 128;
    const int wm = (w & 1) * 64, wn = (w >> 1) * 32;
    if (tid < 128) bias_s[tid] = bias[n0 + tid];

    FragC acc[4][2];
    #pragma unroll
    for (int i = 0; i < 4; i++)
        #pragma unroll
        for (int j = 0; j < 2; j++) wmma::fill_fragment(acc[i][j], 0.0f);

    const int r = tid >> 1;
    const int c0 = (tid & 1) * 16;
    const float* xp = X + (size_t)(m0 + r) * HH + c0;
    const float* wp = W + (size_t)(n0 + r) * HH + c0;

    for (int s = 0; s < NSLAB; s++) {
        // 64-col slab: each thread covers cols c0 and c0+32 of its row
        #pragma unroll
        for (int hh2 = 0; hh2 < 2; hh2++) {
            const int co = hh2 * 32;
            #pragma unroll
            for (int i = 0; i < 4; i++) {
                float4 t4 = *(const float4*)(xp + s * SLABK + co + i * 4);
                CVT4(t4); *(float4*)&As[r * LDS + c0 + co + i * 4] = t4;
                float4 u4 = *(const float4*)(wp + s * SLABK + co + i * 4);
                CVT4(u4); *(float4*)&Bs[r * LDS + c0 + co + i * 4] = u4;
            }
        }
        __syncthreads();
        #pragma unroll
        for (int kk = 0; kk < 8; kk++) {
            FragA a[4]; FragBc b[2];
            #pragma unroll
            for (int i = 0; i < 4; i++) wmma::load_matrix_sync(a[i], &As[(wm + i * 16) * LDS + kk * 8], LDS);
            #pragma unroll
            for (int j = 0; j < 2; j++) wmma::load_matrix_sync(b[j], &Bs[(wn + j * 16) * LDS + kk * 8], LDS);
            #pragma unroll
            for (int i = 0; i < 4; i++)
                #pragma unroll
                for (int j = 0; j < 2; j++) wmma::mma_sync(acc[i][j], a[i], b[j], acc[i][j]);
        }
        __syncthreads();
    }

    #pragma unroll
    for (int i = 0; i < 4; i++)
        #pragma unroll
        for (int j = 0; j < 2; j++)
            wmma::store_matrix_sync(&Cs[(wm + i * 16) * LDQ + wn + j * 16], acc[i][j], LDQ, wmma::mem_row_major);
    __syncthreads();

    {
        const int rr = tid >> 1;
        const int cc = (tid & 1) * 64;
        const int h = (n0 + cc) >> 6;
        const int m = m0 + rr, b = m >> 11, s = m & 2047;
        float* dst = &Y[(((size_t)b * NH + h) * SS + s) * DD];
        #pragma unroll
        for (int t = 0; t < 16; t++) {
            float4 t4 = *(float4*)&Cs[rr * LDQ + cc + t * 4];
            t4.x += bias_s[cc + t * 4];     t4.y += bias_s[cc + t * 4 + 1];
            t4.z += bias_s[cc + t * 4 + 2]; t4.w += bias_s[cc + t * 4 + 3];
            *(float4*)&dst[t * 4] = t4;
        }
    }
}

// ============================================================
// Kernel 2: fused attention, K-split 2-way, 128-row Q tiles,
// 2 CTA/SM, register prefetch, warp-local exp, and a named
// pair-barrier (64 threads) for the exp->AV sync.
// ============================================================
__global__ void __launch_bounds__(256, 2)
fused_attn_kernel(const int* __restrict__ mask, float* __restrict__ attn) {
    extern __shared__ float sm[];
    float* Qs    = sm;                    // [128][LDP]
    float* Ks    = Qs + 128 * LDP;        // [64][LDP]
    float* Vs    = Ks + 64 * LDP;         // [64][LDP]
    float* ps    = Vs + 64 * LDP;         // [128][LDP]
    float* biasv = ps + 128 * LDP;        // [KHALF]
    float* lsmem = biasv + KHALF;         // [128][2]

    const int tid = threadIdx.x;
    const int w = tid >> 5;
    const int lane = tid & 31;
    const int bh = blockIdx.y;
    const int b = bh / NH, h = bh % NH;
    const int m0 = blockIdx.x * 128;
    const int half = blockIdx.z;
    const int kbase = half * KHALF;
    const int wm = (w >> 1) * 32, wn = (w & 1) * 32;
    const int pair_bar = (w >> 1) + 1;    // named barrier id 1..4

    const float* qh_head = g_qh + (size_t)bh * SS * DD + (size_t)m0 * DD;
    const float* kh_head = g_kh + (size_t)bh * SS * DD;
    const float* vh_head = g_vh + (size_t)bh * SS * DD;

    #pragma unroll
    for (int jj = 0; jj < 2; jj++) {
        int e = tid + 256 * jj;
        int r = e >> 2, cc = (e & 3) * 16;
        #pragma unroll
        for (int i = 0; i < 4; i++) {
            float4 t4 = *(const float4*)&qh_head[(size_t)r * DD + cc + i * 4];
            CVT4(t4);
            *(float4*)&Qs[r * LDP + cc + i * 4] = t4;
        }
    }
    #pragma unroll
    for (int i = 0; i < 4; i++) {
        int c = tid + 256 * i;
        biasv[c] = mask[b * SS + kbase + c] ? MASK_B2 : 0.0f;
    }

    // warp-local exp mapping: rows wm+r2 / wm+16+r2, cols wn + hl*4 + i*8
    const int r2 = lane >> 1;
    const int hl = lane & 1;
    const int rowA = wm + r2, rowB = wm + 16 + r2;
    float* arowA = attn + ((size_t)bh * SS + m0 + rowA) * SS + kbase;
    float* arowB = attn + ((size_t)bh * SS + m0 + rowB) * SS + kbase;
    float lsumA = 0.0f, lsumB = 0.0f;

    const int kvr = tid >> 2, kvc = (tid & 3) * 16;   // K/V load mapping

    FragC accv[2][2];
    #pragma unroll
    for (int i = 0; i < 2; i++)
        #pragma unroll
        for (int j = 0; j < 2; j++) wmma::fill_fragment(accv[i][j], 0.0f);

    // prefetch chunk 0 K/V into registers
    float4 kpre[4], vpre[4];
    {
        const float* ksrc = kh_head + (size_t)(kbase + kvr) * DD + kvc;
        const float* vsrc = vh_head + (size_t)(kbase + kvr) * DD + kvc;
        #pragma unroll
        for (int i = 0; i < 4; i++) {
            kpre[i] = *(const float4*)(ksrc + i * 4);
            vpre[i] = *(const float4*)(vsrc + i * 4);
        }
    }
    __syncthreads();   // also covers Qs/biasv init

    for (int cl = 0; cl < KHALF; cl += 64) {
        // ---- store prefetched K/V regs to smem (tf32) ----
        #pragma unroll
        for (int i = 0; i < 4; i++) {
            float4 t4 = kpre[i];
            CVT4(t4); *(float4*)&Ks[kvr * LDP + kvc + i * 4] = t4;
            float4 u4 = vpre[i];
            CVT4(u4); *(float4*)&Vs[kvr * LDP + kvc + i * 4] = u4;
        }
        __syncthreads();                                    // B1 (CTA-wide)

        // ---- S = Q @ K^T (warp subtile 32x32) ----
        {
            FragC sa[2][2];
            #pragma unroll
            for (int i = 0; i < 2; i++)
                #pragma unroll
                for (int j = 0; j < 2; j++) wmma::fill_fragment(sa[i][j], 0.0f);
            #pragma unroll
            for (int kk = 0; kk < 8; kk++) {
                FragA a0, a1; FragBc b0, b1;
                wmma::load_matrix_sync(a0, &Qs[(wm +  0) * LDP + kk * 8], LDP);
                wmma::load_matrix_sync(a1, &Qs[(wm + 16) * LDP + kk * 8], LDP);
                wmma::load_matrix_sync(b0, &Ks[(wn +  0) * LDP + kk * 8], LDP);
                wmma::load_matrix_sync(b1, &Ks[(wn + 16) * LDP + kk * 8], LDP);
                wmma::mma_sync(sa[0][0], a0, b0, sa[0][0]);
                wmma::mma_sync(sa[0][1], a0, b1, sa[0][1]);
                wmma::mma_sync(sa[1][0], a1, b0, sa[1][0]);
                wmma::mma_sync(sa[1][1], a1, b1, sa[1][1]);
            }
            #pragma unroll
            for (int i = 0; i < 2; i++)
                #pragma unroll
                for (int j = 0; j < 2; j++)
                    wmma::store_matrix_sync(&ps[(wm + i * 16) * LDP + wn + j * 16], sa[i][j], LDP, wmma::mem_row_major);
        }

        // ---- WARP-LOCAL exp on own 32x32 subtile ----
        {
            #pragma unroll
            for (int i = 0; i < 4; i++) {
                int c = wn + hl * 4 + i * 8;
                float4 bA = *(const float4*)&biasv[cl + c];
                float4 tA = *(float4*)&ps[rowA * LDP + c];
                float4 pA;
                pA.x = exp2_mufu(fmaf(tA.x, SC_L2E, bA.x));
                pA.y = exp2_mufu(fmaf(tA.y, SC_L2E, bA.y));
                pA.z = exp2_mufu(fmaf(tA.z, SC_L2E, bA.z));
                pA.w = exp2_mufu(fmaf(tA.w, SC_L2E, bA.w));
                lsumA += pA.x + pA.y + pA.z + pA.w;
                *(float4*)&arowA[cl + c] = pA;
                CVT4(pA);
                *(float4*)&ps[rowA * LDP + c] = pA;

                float4 tB = *(float4*)&ps[rowB * LDP + c];
                float4 pB;
                pB.x = exp2_mufu(fmaf(tB.x, SC_L2E, bA.x));
                pB.y = exp2_mufu(fmaf(tB.y, SC_L2E, bA.y));
                pB.z = exp2_mufu(fmaf(tB.z, SC_L2E, bA.z));
                pB.w = exp2_mufu(fmaf(tB.w, SC_L2E, bA.w));
                lsumB += pB.x + pB.y + pB.z + pB.w;
                *(float4*)&arowB[cl + c] = pB;
                CVT4(pB);
                *(float4*)&ps[rowB * LDP + c] = pB;
            }
        }
        // B2: only the 2 col-warps of this row group must agree on ps rows
        asm volatile("bar.sync %0, %1;" :: "r"(pair_bar), "r"(64) : "memory");

        // ---- issue prefetch for next chunk (overlaps AV MMAs) ----
        if (cl + 64 < KHALF) {
            const int cn = kbase + cl + 64;
            const float* ksrc = kh_head + (size_t)(cn + kvr) * DD + kvc;
            const float* vsrc = vh_head + (size_t)(cn + kvr) * DD + kvc;
            #pragma unroll
            for (int i = 0; i < 4; i++) {
                kpre[i] = *(const float4*)(ksrc + i * 4);
                vpre[i] = *(const float4*)(vsrc + i * 4);
            }
        }

        // ---- AV accumulate: accv += P(128x64) @ V(64x64) ----
        #pragma unroll
        for (int kk = 0; kk < 8; kk++) {
            FragA a0, a1; FragBr b0, b1;
            wmma::load_matrix_sync(a0, &ps[(wm +  0) * LDP + kk * 8], LDP);
            wmma::load_matrix_sync(a1, &ps[(wm + 16) * LDP + kk * 8], LDP);
            wmma::load_matrix_sync(b0, &Vs[(kk * 8) * LDP + wn +  0], LDP);
            wmma::load_matrix_sync(b1, &Vs[(kk * 8) * LDP + wn + 16], LDP);
            wmma::mma_sync(accv[0][0], a0, b0, accv[0][0]);
            wmma::mma_sync(accv[0][1], a0, b1, accv[0][1]);
            wmma::mma_sync(accv[1][0], a1, b0, accv[1][0]);
            wmma::mma_sync(accv[1][1], a1, b1, accv[1][1]);
        }
        __syncthreads();                                    // B3 (CTA-wide)
    }

    // ---- combine row sums across the 2 col-warps via smem ----
    lsumA += __shfl_xor_sync(0xFFFFFFFFu, lsumA, 1);
    lsumB += __shfl_xor_sync(0xFFFFFFFFu, lsumB, 1);
    if (hl == 0) {
        lsmem[rowA * 2 + (w & 1)] = lsumA;
        lsmem[rowB * 2 + (w & 1)] = lsumB;
    }
    __syncthreads();
    if (tid < 128)
        g_lpart[half][bh * SS + m0 + tid] = lsmem[tid * 2] + lsmem[tid * 2 + 1];

    // ---- store AV accumulators, write unnormalized ctx partial ----
    #pragma unroll
    for (int i = 0; i < 2; i++)
        #pragma unroll
        for (int j = 0; j < 2; j++)
            wmma::store_matrix_sync(&ps[(wm + i * 16) * LDP + wn + j * 16], accv[i][j], LDP, wmma::mem_row_major);
    __syncthreads();
    {
        const int erow = tid >> 1;
        const int cb = (tid & 1) * 4;
        float* dst = &g_cpart[half][((size_t)(b * SS + m0 + erow)) * HH + h * 64];
        #pragma unroll
        for (int i = 0; i < 8; i++) {
            int c = cb + i * 8;
            float4 t4 = *(float4*)&ps[erow * LDP + c];
            *(float4*)&dst[c] = t4;
        }
    }
}

// ============================================================
// Kernel 3: combine partial AV halves: ctx = (P0+P1)/(l0+l1).
// ============================================================
__global__ void __launch_bounds__(192)
combine_ctx_kernel() {
    const int row = blockIdx.x;           // b*SS + s
    const int b = row >> 11, s = row & 2047;
    __shared__ float inv_s[NH];
    if (threadIdx.x < NH) {
        int li = (b * NH + threadIdx.x) * SS + s;
        inv_s[threadIdx.x] = 1.0f / (g_lpart[0][li] + g_lpart[1][li]);
    }
    __syncthreads();
    const int n = threadIdx.x * 4;
    const float inv = inv_s[n >> 6];
    const size_t base = (size_t)row * HH + n;
    float4 a = *(const float4*)&g_cpart[0][base];
    float4 c = *(const float4*)&g_cpart[1][base];
    a.x = (a.x + c.x) * inv; a.y = (a.y + c.y) * inv;
    a.z = (a.z + c.z) * inv; a.w = (a.w + c.w) * inv;
    *(float4*)&g_ctx[base] = a;
}

// ============================================================
// Kernel 4: attn rescale (block per row, coalesced streaming).
// ============================================================
__global__ void __launch_bounds__(256)
attn_scale_kernel(float* __restrict__ attn) {
    const int row = blockIdx.x;
    const float inv = 1.0f / (g_lpart[0][row] + g_lpart[1][row]);
    float* p = attn + (size_t)row * SS;
    const int t = threadIdx.x;
    #pragma unroll
    for (int i = 0; i < 2; i++) {
        int c = (t + i * 256) * 4;
        float4 v4 = *(float4*)&p[c];
        v4.x *= inv; v4.y *= inv; v4.z *= inv; v4.w *= inv;
        *(float4*)&p[c] = v4;
    }
}

// ============================================================
// Kernel 5: out = ctx @ Wm^T + bm (128x64 tile, 16-k slab).
// ============================================================
__global__ void __launch_bounds__(256)
out_proj_kernel(const float* __restrict__ Wm,
                const float* __restrict__ bm,
                float* __restrict__ out) {
    __shared__ float sbuf[128 * LDP];
    __shared__ float bias_s[64];
    float* As = sbuf;
    float* Bs = sbuf + 128 * LDT;
    float* Cs = sbuf;

    const int tid = threadIdx.x;
    const int w = tid >> 5;
    const int m0 = blockIdx.y * 128, n0 = blockIdx.x * 64;
    const int mw = (w >> 1) * 32, nw = (w & 1) * 32;
    if (tid < 64) bias_s[tid] = bm[n0 + tid];

    FragC acc[2][2];
    #pragma unroll
    for (int i = 0; i < 2; i++)
        #pragma unroll
        for (int j = 0; j < 2; j++) wmma::fill_fragment(acc[i][j], 0.0f);

    for (int k0 = 0; k0 < HH; k0 += 16) {
        #pragma unroll
        for (int jj = 0; jj < 2; jj++) {
            int e = tid + 256 * jj;
            int r = e >> 2, c4 = (e & 3) * 4;
            float4 t4 = *(const float4*)&g_ctx[(size_t)(m0 + r) * HH + k0 + c4];
            CVT4(t4);
            *(float4*)&As[r * LDT + c4] = t4;
        }
        {
            int r = tid >> 2, c4 = (tid & 3) * 4;
            float4 t4 = *(const float4*)&Wm[(size_t)(n0 + r) * HH + k0 + c4];
            CVT4(t4);
            *(float4*)&Bs[r * LDT + c4] = t4;
        }
        __syncthreads();
        #pragma unroll
        for (int kt = 0; kt < 2; kt++) {
            FragA a0, a1; FragBc b0, b1;
            wmma::load_matrix_sync(a0, &As[(mw +  0) * LDT + kt * 8], LDT);
            wmma::load_matrix_sync(a1, &As[(mw + 16) * LDT + kt * 8], LDT);
            wmma::load_matrix_sync(b0, &Bs[(nw +  0) * LDT + kt * 8], LDT);
            wmma::load_matrix_sync(b1, &Bs[(nw + 16) * LDT + kt * 8], LDT);
            wmma::mma_sync(acc[0][0], a0, b0, acc[0][0]);
            wmma::mma_sync(acc[0][1], a0, b1, acc[0][1]);
            wmma::mma_sync(acc[1][0], a1, b0, acc[1][0]);
            wmma::mma_sync(acc[1][1], a1, b1, acc[1][1]);
        }
        __syncthreads();
    }
    #pragma unroll
    for (int i = 0; i < 2; i++)
        #pragma unroll
        for (int j = 0; j < 2; j++)
            wmma::store_matrix_sync(&Cs[(mw + i * 16) * LDP + nw + j * 16], acc[i][j], LDP, wmma::mem_row_major);
    __syncthreads();

    #pragma unroll
    for (int jj = 0; jj < 8; jj++) {
        int e = tid + 256 * jj;
        int r = e >> 4, c4 = (e & 15) * 4;
        float4 t4 = *(float4*)&Cs[r * LDP + c4];
        t4.x += bias_s[c4]; t4.y += bias_s[c4 + 1];
        t4.z += bias_s[c4 + 2]; t4.w += bias_s[c4 + 3];
        *(float4*)&out[(size_t)(m0 + r) * HH + n0 + c4] = t4;
    }
}

// ============================================================
// Host launcher — attn_scale overlapped with combine+out_proj.
// ============================================================
extern "C" void kernel_launch(void* const* d_in, const int* in_sizes, int n_in,
                              void* d_out, int out_size) {
    const float* v    = (const float*)d_in[0];
    const float* k    = (const float*)d_in[1];
    const float* q    = (const float*)d_in[2];
    const int*   mask = (const int*)  d_in[3];
    const float* Wv   = (const float*)d_in[4];
    const float* bv   = (const float*)d_in[5];
    const float* Wk   = (const float*)d_in[6];
    const float* bk   = (const float*)d_in[7];
    const float* Wq   = (const float*)d_in[8];
    const float* bq   = (const float*)d_in[9];
    const float* Wm   = (const float*)d_in[10];
    const float* bm   = (const float*)d_in[11];
    float* out = (float*)d_out;

    float* attn;
    if ((size_t)out_size >= (size_t)OUT_ELEMS + ATTN_ELEMS) {
        attn = out + OUT_ELEMS;
    } else {
        void* p = nullptr;
        cudaGetSymbolAddress(&p, g_attn_scratch);
        attn = (float*)p;
    }

    const int SMEM_GEMM = 2 * 128 * LDS * 4;                                               // 69632 (≥ Cs 67584)
    const int SMEM_FA   = (128 * LDP + 64 * LDP + 64 * LDP + 128 * LDP + KHALF + 256) * 4; // 109568
    static int init_done = 0;
    static cudaStream_t s2;
    static cudaEvent_t ev_fork, ev_join;
    if (!init_done) {
        cudaFuncSetAttribute(proj_qkv_kernel, cudaFuncAttributeMaxDynamicSharedMemorySize, SMEM_GEMM);
        cudaFuncSetAttribute(fused_attn_kernel, cudaFuncAttributeMaxDynamicSharedMemorySize, SMEM_FA);
        cudaStreamCreateWithFlags(&s2, cudaStreamNonBlocking);
        cudaEventCreateWithFlags(&ev_fork, cudaEventDisableTiming);
        cudaEventCreateWithFlags(&ev_join, cudaEventDisableTiming);
        init_done = 1;
    }

    proj_qkv_kernel<<<dim3(HH / 128, M_PROJ / 128, 3), 256, SMEM_GEMM>>>(q, k, v, Wq, bq, Wk, bk, Wv, bv);
    fused_attn_kernel<<<dim3(SS / 128, BH, 2), 256, SMEM_FA>>>(mask, attn);

    // fork: attn_scale on s2, concurrent with combine+out_proj on default
    cudaEventRecord(ev_fork, 0);
    cudaStreamWaitEvent(s2, ev_fork, 0);
    attn_scale_kernel<<<BH * SS, 256, 0, s2>>>(attn);
    cudaEventRecord(ev_join, s2);

    combine_ctx_kernel<<<BB * SS, 192>>>();
    out_proj_kernel<<<dim3(HH / 64, M_PROJ / 128, 1), 256>>>(Wm, bm, out);

    // join: default stream waits for attn_scale before returning
    cudaStreamWaitEvent(0, ev_join, 0);
}

// round 16
// speedup vs baseline: 1.3719x; 1.2879x over previous
#include <cuda_runtime.h>
#include <mma.h>
#include <cstdint>
using namespace nvcuda;

#define BB 2
#define SS 2048
#define HH 768
#define NH 12
#define DD 64
#define BH (BB*NH)
#define M_PROJ (BB*SS)
#define OUT_ELEMS (BB*SS*HH)
#define ATTN_ELEMS ((size_t)BB*NH*SS*SS)

__device__ float g_qh[BB*NH*SS*DD];
__device__ float g_kh[BB*NH*SS*DD];
__device__ float g_vh[BB*NH*SS*DD];
__device__ float g_ctx[BB*SS*HH];
__device__ float g_cpart[2][BB*SS*HH];   // unnormalized partial AV per K-half
__device__ float g_lpart[2][BH*SS];      // partial exp-sums per K-half
__device__ float g_attn_scratch[BB*NH*SS*SS];

typedef wmma::fragment<wmma::matrix_a, 16, 16, 8, wmma::precision::tf32, wmma::row_major> FragA;
typedef wmma::fragment<wmma::matrix_b, 16, 16, 8, wmma::precision::tf32, wmma::col_major> FragBc;
typedef wmma::fragment<wmma::accumulator, 16, 16, 8, float> FragC;

#define SLABK 64
#define NSLAB (HH/SLABK) // 12
#define LDS 68           // 64-k slab + 4 pad (proj kernel)
#define LDP 68           // 64 + 4
#define LDQ 132          // 128 + 4
#define LDT 20           // 16-k slab + 4 pad (out_proj kernel)
#define KHALF 1024       // K columns per attention CTA

// log2-domain softmax: p = 2^(s * 0.125*log2(e) + b2); masked b2 = -100
#define SC_L2E 0.18033688011112042f
#define MASK_B2 (-100.0f)

#define CVT4(t4) do { \
    t4.x = wmma::__float_to_tf32(t4.x); t4.y = wmma::__float_to_tf32(t4.y); \
    t4.z = wmma::__float_to_tf32(t4.z); t4.w = wmma::__float_to_tf32(t4.w); } while(0)

__device__ __forceinline__ float exp2_mufu(float y) {
    float r;
    asm("ex2.approx.f32 %0, %1;" : "=f"(r) : "f"(y));
    return r;
}

__device__ __forceinline__ void mma_tf32(float c[4],
    uint32_t a0, uint32_t a1, uint32_t a2, uint32_t a3, uint32_t b0, uint32_t b1) {
    asm volatile(
        "mma.sync.aligned.m16n8k8.row.col.f32.tf32.tf32.f32 "
        "{%0,%1,%2,%3},{%4,%5,%6,%7},{%8,%9},{%0,%1,%2,%3};"
        : "+f"(c[0]), "+f"(c[1]), "+f"(c[2]), "+f"(c[3])
        : "r"(a0), "r"(a1), "r"(a2), "r"(a3), "r"(b0), "r"(b1));
}

// ============================================================
// Kernel 1: fused QKV projections (128x128 tile, 64-k slab).
// ============================================================
__global__ void __launch_bounds__(256, 2)
proj_qkv_kernel(const float* __restrict__ q,
                const float* __restrict__ k,
                const float* __restrict__ v,
                const float* __restrict__ Wq, const float* __restrict__ bq,
                const float* __restrict__ Wk, const float* __restrict__ bk,
                const float* __restrict__ Wv, const float* __restrict__ bv) {
    const float* X; const float* W; const float* bias; float* Y;
    if (blockIdx.z == 0)      { X = q; W = Wq; bias = bq; Y = g_qh; }
    else if (blockIdx.z == 1) { X = k; W = Wk; bias = bk; Y = g_kh; }
    else                      { X = v; W = Wv; bias = bv; Y = g_vh; }

    extern __shared__ float sm[];
    float* As = sm;
    float* Bs = sm + 128 * LDS;
    float* Cs = sm;
    __shared__ float bias_s[128];

    const int tid = threadIdx.x;
    const int w = tid >> 5;
    const int m0 = blockIdx.y * 128, n0 = blockIdx.x * 128;
    const int wm = (w & 1) * 64, wn = (w >> 1) * 32;
    if (tid < 128) bias_s[tid] = bias[n0 + tid];

    FragC acc[4][2];
    #pragma unroll
    for (int i = 0; i < 4; i++)
        #pragma unroll
        for (int j = 0; j < 2; j++) wmma::fill_fragment(acc[i][j], 0.0f);

    const int r = tid >> 1;
    const int c0 = (tid & 1) * 16;
    const float* xp = X + (size_t)(m0 + r) * HH + c0;
    const float* wp = W + (size_t)(n0 + r) * HH + c0;

    for (int s = 0; s < NSLAB; s++) {
        #pragma unroll
        for (int hh2 = 0; hh2 < 2; hh2++) {
            const int co = hh2 * 32;
            #pragma unroll
            for (int i = 0; i < 4; i++) {
                float4 t4 = *(const float4*)(xp + s * SLABK + co + i * 4);
                CVT4(t4); *(float4*)&As[r * LDS + c0 + co + i * 4] = t4;
                float4 u4 = *(const float4*)(wp + s * SLABK + co + i * 4);
                CVT4(u4); *(float4*)&Bs[r * LDS + c0 + co + i * 4] = u4;
            }
        }
        __syncthreads();
        #pragma unroll
        for (int kk = 0; kk < 8; kk++) {
            FragA a[4]; FragBc b[2];
            #pragma unroll
            for (int i = 0; i < 4; i++) wmma::load_matrix_sync(a[i], &As[(wm + i * 16) * LDS + kk * 8], LDS);
            #pragma unroll
            for (int j = 0; j < 2; j++) wmma::load_matrix_sync(b[j], &Bs[(wn + j * 16) * LDS + kk * 8], LDS);
            #pragma unroll
            for (int i = 0; i < 4; i++)
                #pragma unroll
                for (int j = 0; j < 2; j++) wmma::mma_sync(acc[i][j], a[i], b[j], acc[i][j]);
        }
        __syncthreads();
    }

    #pragma unroll
    for (int i = 0; i < 4; i++)
        #pragma unroll
        for (int j = 0; j < 2; j++)
            wmma::store_matrix_sync(&Cs[(wm + i * 16) * LDQ + wn + j * 16], acc[i][j], LDQ, wmma::mem_row_major);
    __syncthreads();

    {
        const int rr = tid >> 1;
        const int cc = (tid & 1) * 64;
        const int h = (n0 + cc) >> 6;
        const int m = m0 + rr, b = m >> 11, s = m & 2047;
        float* dst = &Y[(((size_t)b * NH + h) * SS + s) * DD];
        #pragma unroll
        for (int t = 0; t < 16; t++) {
            float4 t4 = *(float4*)&Cs[rr * LDQ + cc + t * 4];
            t4.x += bias_s[cc + t * 4];     t4.y += bias_s[cc + t * 4 + 1];
            t4.z += bias_s[cc + t * 4 + 2]; t4.w += bias_s[cc + t * 4 + 3];
            *(float4*)&dst[t * 4] = t4;
        }
    }
}

// ============================================================
// Kernel 2: fused attention, register-resident P, ALL-tf32 MMAs.
// S: m16n8k8 tf32; exp in regs; quad-shuffle P into tf32 A-frag
// layout; AV: m16n8k8 tf32 vs Vs smem; 2 barriers/chunk.
// ============================================================
__global__ void __launch_bounds__(256, 2)
fused_attn_kernel(const int* __restrict__ mask, float* __restrict__ attn) {
    extern __shared__ float sm[];
    float* Qs    = sm;                       // [128][LDP]
    float* Ks    = Qs + 128 * LDP;           // [64][LDP]
    float* Vs    = Ks + 64 * LDP;            // [64][LDP]
    float* biasv = Vs + 64 * LDP;            // [KHALF]
    float* lsmem = biasv + KHALF;            // [128][2]

    const int tid = threadIdx.x;
    const int w = tid >> 5;
    const int lane = tid & 31;
    const int g = lane >> 2;
    const int t = lane & 3;
    const int bh = blockIdx.y;
    const int b = bh / NH, h = bh % NH;
    const int m0 = blockIdx.x * 128;
    const int half = blockIdx.z;
    const int kbase = half * KHALF;
    const int wm = (w >> 1) * 32;
    const int wcol = w & 1;
    const int wn = wcol * 32;

    const float* qh_head = g_qh + (size_t)bh * SS * DD + (size_t)m0 * DD;
    const float* kh_head = g_kh + (size_t)bh * SS * DD;
    const float* vh_head = g_vh + (size_t)bh * SS * DD;

    // load Q tile (tf32) + mask bias
    #pragma unroll
    for (int jj = 0; jj < 2; jj++) {
        int e = tid + 256 * jj;
        int r = e >> 2, cc = (e & 3) * 16;
        #pragma unroll
        for (int i = 0; i < 4; i++) {
            float4 t4 = *(const float4*)&qh_head[(size_t)r * DD + cc + i * 4];
            CVT4(t4);
            *(float4*)&Qs[r * LDP + cc + i * 4] = t4;
        }
    }
    #pragma unroll
    for (int i = 0; i < 4; i++) {
        int c = tid + 256 * i;
        biasv[c] = mask[b * SS + kbase + c] ? MASK_B2 : 0.0f;
    }
    __syncthreads();

    const uint32_t* QsU = (const uint32_t*)Qs;
    const uint32_t* KsU = (const uint32_t*)Ks;
    const uint32_t* VsU = (const uint32_t*)Vs;

    // attn row pointers for this thread's 4 fragment rows
    float* ar[4];
    {
        const int rows[4] = { wm + g, wm + g + 8, wm + 16 + g, wm + 16 + g + 8 };
        #pragma unroll
        for (int i = 0; i < 4; i++)
            ar[i] = attn + ((size_t)bh * SS + m0 + rows[i]) * SS + kbase;
    }
    const int coff = wn + 2 * t;
    const int shfl1 = (lane & ~3) | (t >> 1);       // source for cols t
    const int shfl2 = shfl1 + 2;                     // source for cols t+4
    const bool oddc = (t & 1);

    float accv[2][8][4] = {};
    float lsum[2][2] = {};

    for (int cl = 0; cl < KHALF; cl += 64) {
        // ---- load K + V chunk (tf32, row-major [col/k][d]) ----
        {
            int kr = tid >> 2, kc = (tid & 3) * 16;
            const float* ksrc = kh_head + (size_t)(kbase + cl + kr) * DD + kc;
            const float* vsrc = vh_head + (size_t)(kbase + cl + kr) * DD + kc;
            #pragma unroll
            for (int i = 0; i < 4; i++) {
                float4 t4 = *(const float4*)(ksrc + i * 4);
                CVT4(t4); *(float4*)&Ks[kr * LDP + kc + i * 4] = t4;
                float4 u4 = *(const float4*)(vsrc + i * 4);
                CVT4(u4); *(float4*)&Vs[kr * LDP + kc + i * 4] = u4;
            }
        }
        __syncthreads();                                    // B1

        // ---- S = Q @ K^T : warp subtile 32(m) x 32(n), k=64 ----
        float c[2][4][4] = {};
        #pragma unroll
        for (int kk = 0; kk < 8; kk++) {
            uint32_t a[2][4];
            #pragma unroll
            for (int mf = 0; mf < 2; mf++) {
                int base = (wm + mf * 16 + g) * LDP + kk * 8;
                a[mf][0] = QsU[base + t];
                a[mf][1] = QsU[base + 8 * LDP + t];
                a[mf][2] = QsU[base + t + 4];
                a[mf][3] = QsU[base + 8 * LDP + t + 4];
            }
            #pragma unroll
            for (int nf = 0; nf < 4; nf++) {
                int kb = (wn + nf * 8 + g) * LDP + kk * 8;
                uint32_t b0 = KsU[kb + t];
                uint32_t b1 = KsU[kb + t + 4];
                mma_tf32(c[0][nf], a[0][0], a[0][1], a[0][2], a[0][3], b0, b1);
                mma_tf32(c[1][nf], a[1][0], a[1][1], a[1][2], a[1][3], b0, b1);
            }
        }

        // ---- exp in registers + fp32 attn store + row sums ----
        #pragma unroll
        for (int mf = 0; mf < 2; mf++)
            #pragma unroll
            for (int nf = 0; nf < 4; nf++) {
                float2 b2 = *(const float2*)&biasv[cl + coff + nf * 8];
                float p0 = exp2_mufu(fmaf(c[mf][nf][0], SC_L2E, b2.x));
                float p1 = exp2_mufu(fmaf(c[mf][nf][1], SC_L2E, b2.y));
                float p2 = exp2_mufu(fmaf(c[mf][nf][2], SC_L2E, b2.x));
                float p3 = exp2_mufu(fmaf(c[mf][nf][3], SC_L2E, b2.y));
                lsum[mf][0] += p0 + p1;
                lsum[mf][1] += p2 + p3;
                *(float2*)&ar[mf * 2 + 0][cl + coff + nf * 8] = make_float2(p0, p1);
                *(float2*)&ar[mf * 2 + 1][cl + coff + nf * 8] = make_float2(p2, p3);
                c[mf][nf][0] = wmma::__float_to_tf32(p0);
                c[mf][nf][1] = wmma::__float_to_tf32(p1);
                c[mf][nf][2] = wmma::__float_to_tf32(p2);
                c[mf][nf][3] = wmma::__float_to_tf32(p3);
            }

        // ---- AV: per k-step, quad-shuffle P into A-frag, then MMAs ----
        #pragma unroll
        for (int ks = 0; ks < 4; ks++) {
            uint32_t ap[2][4];
            #pragma unroll
            for (int mf = 0; mf < 2; mf++) {
                uint32_t s0 = __float_as_uint(c[mf][ks][0]);
                uint32_t s1 = __float_as_uint(c[mf][ks][1]);
                uint32_t s2 = __float_as_uint(c[mf][ks][2]);
                uint32_t s3 = __float_as_uint(c[mf][ks][3]);
                uint32_t e0 = __shfl_sync(0xFFFFFFFFu, s0, shfl1);
                uint32_t o0 = __shfl_sync(0xFFFFFFFFu, s1, shfl1);
                uint32_t e2 = __shfl_sync(0xFFFFFFFFu, s2, shfl1);
                uint32_t o2 = __shfl_sync(0xFFFFFFFFu, s3, shfl1);
                uint32_t f0 = __shfl_sync(0xFFFFFFFFu, s0, shfl2);
                uint32_t g0 = __shfl_sync(0xFFFFFFFFu, s1, shfl2);
                uint32_t f2 = __shfl_sync(0xFFFFFFFFu, s2, shfl2);
                uint32_t g2 = __shfl_sync(0xFFFFFFFFu, s3, shfl2);
                ap[mf][0] = oddc ? o0 : e0;   // (row g,    col t)
                ap[mf][1] = oddc ? o2 : e2;   // (row g+8,  col t)
                ap[mf][2] = oddc ? g0 : f0;   // (row g,    col t+4)
                ap[mf][3] = oddc ? g2 : f2;   // (row g+8,  col t+4)
            }
            #pragma unroll
            for (int dn = 0; dn < 8; dn++) {
                uint32_t b0 = VsU[(wn + ks * 8 + t) * LDP + dn * 8 + g];
                uint32_t b1 = VsU[(wn + ks * 8 + t + 4) * LDP + dn * 8 + g];
                mma_tf32(accv[0][dn], ap[0][0], ap[0][1], ap[0][2], ap[0][3], b0, b1);
                mma_tf32(accv[1][dn], ap[1][0], ap[1][1], ap[1][2], ap[1][3], b0, b1);
            }
        }
        __syncthreads();                                    // B2
    }

    // ---- row sums: reduce over t-quad, publish via lsmem ----
    #pragma unroll
    for (int mf = 0; mf < 2; mf++)
        #pragma unroll
        for (int rr = 0; rr < 2; rr++) {
            float v = lsum[mf][rr];
            v += __shfl_xor_sync(0xFFFFFFFFu, v, 1);
            v += __shfl_xor_sync(0xFFFFFFFFu, v, 2);
            if (t == 0)
                lsmem[(wm + mf * 16 + g + rr * 8) * 2 + wcol] = v;
        }

    // ---- combine the two k-partial accv sets via smem (reuse Qs) ----
    if (wcol == 0) {
        #pragma unroll
        for (int mf = 0; mf < 2; mf++)
            #pragma unroll
            for (int dn = 0; dn < 8; dn++) {
                int r0 = wm + mf * 16 + g;
                *(float2*)&Qs[r0 * LDP + dn * 8 + 2 * t]       = make_float2(accv[mf][dn][0], accv[mf][dn][1]);
                *(float2*)&Qs[(r0 + 8) * LDP + dn * 8 + 2 * t] = make_float2(accv[mf][dn][2], accv[mf][dn][3]);
            }
    }
    __syncthreads();
    if (wcol == 1) {
        #pragma unroll
        for (int mf = 0; mf < 2; mf++)
            #pragma unroll
            for (int dn = 0; dn < 8; dn++) {
                int r0 = wm + mf * 16 + g;
                float2* p0 = (float2*)&Qs[r0 * LDP + dn * 8 + 2 * t];
                float2* p1 = (float2*)&Qs[(r0 + 8) * LDP + dn * 8 + 2 * t];
                float2 x0 = *p0, x1 = *p1;
                x0.x += accv[mf][dn][0]; x0.y += accv[mf][dn][1];
                x1.x += accv[mf][dn][2]; x1.y += accv[mf][dn][3];
                *p0 = x0; *p1 = x1;
            }
    }
    if (tid < 128)
        g_lpart[half][bh * SS + m0 + tid] = lsmem[tid * 2] + lsmem[tid * 2 + 1];
    __syncthreads();

    // ---- write unnormalized ctx partial ----
    {
        const int erow = tid >> 1;
        const int cb = (tid & 1) * 4;
        float* dst = &g_cpart[half][((size_t)(b * SS + m0 + erow)) * HH + h * 64];
        #pragma unroll
        for (int i = 0; i < 8; i++) {
            int cc = cb + i * 8;
            *(float4*)&dst[cc] = *(float4*)&Qs[erow * LDP + cc];
        }
    }
}

// ============================================================
// Kernel 3: combine partial AV halves: ctx = (P0+P1)/(l0+l1).
// ============================================================
__global__ void __launch_bounds__(192)
combine_ctx_kernel() {
    const int row = blockIdx.x;           // b*SS + s
    const int b = row >> 11, s = row & 2047;
    __shared__ float inv_s[NH];
    if (threadIdx.x < NH) {
        int li = (b * NH + threadIdx.x) * SS + s;
        inv_s[threadIdx.x] = 1.0f / (g_lpart[0][li] + g_lpart[1][li]);
    }
    __syncthreads();
    const int n = threadIdx.x * 4;
    const float inv = inv_s[n >> 6];
    const size_t base = (size_t)row * HH + n;
    float4 a = *(const float4*)&g_cpart[0][base];
    float4 c = *(const float4*)&g_cpart[1][base];
    a.x = (a.x + c.x) * inv; a.y = (a.y + c.y) * inv;
    a.z = (a.z + c.z) * inv; a.w = (a.w + c.w) * inv;
    *(float4*)&g_ctx[base] = a;
}

// ============================================================
// Kernel 4: attn rescale (block per row, coalesced streaming).
// ============================================================
__global__ void __launch_bounds__(256)
attn_scale_kernel(float* __restrict__ attn) {
    const int row = blockIdx.x;
    const float inv = 1.0f / (g_lpart[0][row] + g_lpart[1][row]);
    float* p = attn + (size_t)row * SS;
    const int t = threadIdx.x;
    #pragma unroll
    for (int i = 0; i < 2; i++) {
        int c = (t + i * 256) * 4;
        float4 v4 = *(float4*)&p[c];
        v4.x *= inv; v4.y *= inv; v4.z *= inv; v4.w *= inv;
        *(float4*)&p[c] = v4;
    }
}

// ============================================================
// Kernel 5: out = ctx @ Wm^T + bm (128x64 tile, 16-k slab).
// ============================================================
__global__ void __launch_bounds__(256)
out_proj_kernel(const float* __restrict__ Wm,
                const float* __restrict__ bm,
                float* __restrict__ out) {
    __shared__ float sbuf[128 * LDP];
    __shared__ float bias_s[64];
    float* As = sbuf;
    float* Bs = sbuf + 128 * LDT;
    float* Cs = sbuf;

    const int tid = threadIdx.x;
    const int w = tid >> 5;
    const int m0 = blockIdx.y * 128, n0 = blockIdx.x * 64;
    const int mw = (w >> 1) * 32, nw = (w & 1) * 32;
    if (tid < 64) bias_s[tid] = bm[n0 + tid];

    FragC acc[2][2];
    #pragma unroll
    for (int i = 0; i < 2; i++)
        #pragma unroll
        for (int j = 0; j < 2; j++) wmma::fill_fragment(acc[i][j], 0.0f);

    for (int k0 = 0; k0 < HH; k0 += 16) {
        #pragma unroll
        for (int jj = 0; jj < 2; jj++) {
            int e = tid + 256 * jj;
            int r = e >> 2, c4 = (e & 3) * 4;
            float4 t4 = *(const float4*)&g_ctx[(size_t)(m0 + r) * HH + k0 + c4];
            CVT4(t4);
            *(float4*)&As[r * LDT + c4] = t4;
        }
        {
            int r = tid >> 2, c4 = (tid & 3) * 4;
            float4 t4 = *(const float4*)&Wm[(size_t)(n0 + r) * HH + k0 + c4];
            CVT4(t4);
            *(float4*)&Bs[r * LDT + c4] = t4;
        }
        __syncthreads();
        #pragma unroll
        for (int kt = 0; kt < 2; kt++) {
            FragA a0, a1; FragBc b0, b1;
            wmma::load_matrix_sync(a0, &As[(mw +  0) * LDT + kt * 8], LDT);
            wmma::load_matrix_sync(a1, &As[(mw + 16) * LDT + kt * 8], LDT);
            wmma::load_matrix_sync(b0, &Bs[(nw +  0) * LDT + kt * 8], LDT);
            wmma::load_matrix_sync(b1, &Bs[(nw + 16) * LDT + kt * 8], LDT);
            wmma::mma_sync(acc[0][0], a0, b0, acc[0][0]);
            wmma::mma_sync(acc[0][1], a0, b1, acc[0][1]);
            wmma::mma_sync(acc[1][0], a1, b0, acc[1][0]);
            wmma::mma_sync(acc[1][1], a1, b1, acc[1][1]);
        }
        __syncthreads();
    }
    #pragma unroll
    for (int i = 0; i < 2; i++)
        #pragma unroll
        for (int j = 0; j < 2; j++)
            wmma::store_matrix_sync(&Cs[(mw + i * 16) * LDP + nw + j * 16], acc[i][j], LDP, wmma::mem_row_major);
    __syncthreads();

    #pragma unroll
    for (int jj = 0; jj < 8; jj++) {
        int e = tid + 256 * jj;
        int r = e >> 4, c4 = (e & 15) * 4;
        float4 t4 = *(float4*)&Cs[r * LDP + c4];
        t4.x += bias_s[c4]; t4.y += bias_s[c4 + 1];
        t4.z += bias_s[c4 + 2]; t4.w += bias_s[c4 + 3];
        *(float4*)&out[(size_t)(m0 + r) * HH + n0 + c4] = t4;
    }
}

// ============================================================
// Host launcher — attn_scale overlapped with combine+out_proj.
// ============================================================
extern "C" void kernel_launch(void* const* d_in, const int* in_sizes, int n_in,
                              void* d_out, int out_size) {
    const float* v    = (const float*)d_in[0];
    const float* k    = (const float*)d_in[1];
    const float* q    = (const float*)d_in[2];
    const int*   mask = (const int*)  d_in[3];
    const float* Wv   = (const float*)d_in[4];
    const float* bv   = (const float*)d_in[5];
    const float* Wk   = (const float*)d_in[6];
    const float* bk   = (const float*)d_in[7];
    const float* Wq   = (const float*)d_in[8];
    const float* bq   = (const float*)d_in[9];
    const float* Wm   = (const float*)d_in[10];
    const float* bm   = (const float*)d_in[11];
    float* out = (float*)d_out;

    float* attn;
    if ((size_t)out_size >= (size_t)OUT_ELEMS + ATTN_ELEMS) {
        attn = out + OUT_ELEMS;
    } else {
        void* p = nullptr;
        cudaGetSymbolAddress(&p, g_attn_scratch);
        attn = (float*)p;
    }

    const int SMEM_GEMM = 2 * 128 * LDS * 4;                                    // 69632
    const int SMEM_FA   = (256 * LDP + KHALF + 256) * 4;                        // 74752
    static int init_done = 0;
    static cudaStream_t s2;
    static cudaEvent_t ev_fork, ev_join;
    if (!init_done) {
        cudaFuncSetAttribute(proj_qkv_kernel, cudaFuncAttributeMaxDynamicSharedMemorySize, SMEM_GEMM);
        cudaFuncSetAttribute(fused_attn_kernel, cudaFuncAttributeMaxDynamicSharedMemorySize, SMEM_FA);
        cudaStreamCreateWithFlags(&s2, cudaStreamNonBlocking);
        cudaEventCreateWithFlags(&ev_fork, cudaEventDisableTiming);
        cudaEventCreateWithFlags(&ev_join, cudaEventDisableTiming);
        init_done = 1;
    }

    proj_qkv_kernel<<<dim3(HH / 128, M_PROJ / 128, 3), 256, SMEM_GEMM>>>(q, k, v, Wq, bq, Wk, bk, Wv, bv);
    fused_attn_kernel<<<dim3(SS / 128, BH, 2), 256, SMEM_FA>>>(mask, attn);

    // fork: attn_scale on s2, concurrent with combine+out_proj on default
    cudaEventRecord(ev_fork, 0);
    cudaStreamWaitEvent(s2, ev_fork, 0);
    attn_scale_kernel<<<BH * SS, 256, 0, s2>>>(attn);
    cudaEventRecord(ev_join, s2);

    combine_ctx_kernel<<<BB * SS, 192>>>();
    out_proj_kernel<<<dim3(HH / 64, M_PROJ / 128, 1), 256>>>(Wm, bm, out);

    // join: default stream waits for attn_scale before returning
    cudaStreamWaitEvent(0, ev_join, 0);
}

// round 17
// speedup vs baseline: 1.4265x; 1.0398x over previous
#include <cuda_runtime.h>
#include <mma.h>
#include <cstdint>
using namespace nvcuda;

#define BB 2
#define SS 2048
#define HH 768
#define NH 12
#define DD 64
#define BH (BB*NH)
#define M_PROJ (BB*SS)
#define OUT_ELEMS (BB*SS*HH)
#define ATTN_ELEMS ((size_t)BB*NH*SS*SS)

__device__ float g_qh[BB*NH*SS*DD];
__device__ float g_kh[BB*NH*SS*DD];
__device__ float g_vh[BB*NH*SS*DD];
__device__ float g_ctx[BB*SS*HH];
__device__ float g_cpart[2][BB*SS*HH];   // unnormalized partial AV per K-half
__device__ float g_lpart[2][BH*SS];      // partial exp-sums per K-half
__device__ float g_attn_scratch[BB*NH*SS*SS];

typedef wmma::fragment<wmma::matrix_a, 16, 16, 8, wmma::precision::tf32, wmma::row_major> FragA;
typedef wmma::fragment<wmma::matrix_b, 16, 16, 8, wmma::precision::tf32, wmma::col_major> FragBc;
typedef wmma::fragment<wmma::accumulator, 16, 16, 8, float> FragC;

#define SLABK 64
#define NSLAB (HH/SLABK) // 12
#define LDS 68           // 64-k slab + 4 pad (proj kernel)
#define LDP 68           // 64 + 4
#define LDQ 132          // 128 + 4
#define LDT 20           // 16-k slab + 4 pad (out_proj kernel)
#define KHALF 1024       // K columns per attention CTA

// log2-domain softmax: p = 2^(s * 0.125*log2(e) + b2); masked b2 = -100
#define SC_L2E 0.18033688011112042f
#define MASK_B2 (-100.0f)

#define CVT4(t4) do { \
    t4.x = wmma::__float_to_tf32(t4.x); t4.y = wmma::__float_to_tf32(t4.y); \
    t4.z = wmma::__float_to_tf32(t4.z); t4.w = wmma::__float_to_tf32(t4.w); } while(0)

__device__ __forceinline__ float exp2_mufu(float y) {
    float r;
    asm("ex2.approx.f32 %0, %1;" : "=f"(r) : "f"(y));
    return r;
}

__device__ __forceinline__ void mma_tf32(float c[4],
    uint32_t a0, uint32_t a1, uint32_t a2, uint32_t a3, uint32_t b0, uint32_t b1) {
    asm volatile(
        "mma.sync.aligned.m16n8k8.row.col.f32.tf32.tf32.f32 "
        "{%0,%1,%2,%3},{%4,%5,%6,%7},{%8,%9},{%0,%1,%2,%3};"
        : "+f"(c[0]), "+f"(c[1]), "+f"(c[2]), "+f"(c[3])
        : "r"(a0), "r"(a1), "r"(a2), "r"(a3), "r"(b0), "r"(b1));
}

__device__ __forceinline__ void cp_async16(uint32_t smem_addr, const void* gptr) {
    asm volatile("cp.async.cg.shared.global [%0], [%1], 16;" :: "r"(smem_addr), "l"(gptr));
}
#define CP_COMMIT() asm volatile("cp.async.commit_group;" ::: "memory")
#define CP_WAIT1()  asm volatile("cp.async.wait_group 1;" ::: "memory")
#define CP_WAIT0()  asm volatile("cp.async.wait_group 0;" ::: "memory")

// ============================================================
// Kernel 1: fused QKV projections (128x128 tile, 64-k slab).
// Outputs pre-rounded to tf32 (consumed only by fused_attn).
// ============================================================
__global__ void __launch_bounds__(256, 2)
proj_qkv_kernel(const float* __restrict__ q,
                const float* __restrict__ k,
                const float* __restrict__ v,
                const float* __restrict__ Wq, const float* __restrict__ bq,
                const float* __restrict__ Wk, const float* __restrict__ bk,
                const float* __restrict__ Wv, const float* __restrict__ bv) {
    const float* X; const float* W; const float* bias; float* Y;
    if (blockIdx.z == 0)      { X = q; W = Wq; bias = bq; Y = g_qh; }
    else if (blockIdx.z == 1) { X = k; W = Wk; bias = bk; Y = g_kh; }
    else                      { X = v; W = Wv; bias = bv; Y = g_vh; }

    extern __shared__ float sm[];
    float* As = sm;
    float* Bs = sm + 128 * LDS;
    float* Cs = sm;
    __shared__ float bias_s[128];

    const int tid = threadIdx.x;
    const int w = tid >> 5;
    const int m0 = blockIdx.y * 128, n0 = blockIdx.x * 128;
    const int wm = (w & 1) * 64, wn = (w >> 1) * 32;
    if (tid < 128) bias_s[tid] = bias[n0 + tid];

    FragC acc[4][2];
    #pragma unroll
    for (int i = 0; i < 4; i++)
        #pragma unroll
        for (int j = 0; j < 2; j++) wmma::fill_fragment(acc[i][j], 0.0f);

    const int r = tid >> 1;
    const int c0 = (tid & 1) * 16;
    const float* xp = X + (size_t)(m0 + r) * HH + c0;
    const float* wp = W + (size_t)(n0 + r) * HH + c0;

    for (int s = 0; s < NSLAB; s++) {
        #pragma unroll
        for (int hh2 = 0; hh2 < 2; hh2++) {
            const int co = hh2 * 32;
            #pragma unroll
            for (int i = 0; i < 4; i++) {
                float4 t4 = *(const float4*)(xp + s * SLABK + co + i * 4);
                CVT4(t4); *(float4*)&As[r * LDS + c0 + co + i * 4] = t4;
                float4 u4 = *(const float4*)(wp + s * SLABK + co + i * 4);
                CVT4(u4); *(float4*)&Bs[r * LDS + c0 + co + i * 4] = u4;
            }
        }
        __syncthreads();
        #pragma unroll
        for (int kk = 0; kk < 8; kk++) {
            FragA a[4]; FragBc b[2];
            #pragma unroll
            for (int i = 0; i < 4; i++) wmma::load_matrix_sync(a[i], &As[(wm + i * 16) * LDS + kk * 8], LDS);
            #pragma unroll
            for (int j = 0; j < 2; j++) wmma::load_matrix_sync(b[j], &Bs[(wn + j * 16) * LDS + kk * 8], LDS);
            #pragma unroll
            for (int i = 0; i < 4; i++)
                #pragma unroll
                for (int j = 0; j < 2; j++) wmma::mma_sync(acc[i][j], a[i], b[j], acc[i][j]);
        }
        __syncthreads();
    }

    #pragma unroll
    for (int i = 0; i < 4; i++)
        #pragma unroll
        for (int j = 0; j < 2; j++)
            wmma::store_matrix_sync(&Cs[(wm + i * 16) * LDQ + wn + j * 16], acc[i][j], LDQ, wmma::mem_row_major);
    __syncthreads();

    {
        const int rr = tid >> 1;
        const int cc = (tid & 1) * 64;
        const int h = (n0 + cc) >> 6;
        const int m = m0 + rr, b = m >> 11, s = m & 2047;
        float* dst = &Y[(((size_t)b * NH + h) * SS + s) * DD];
        #pragma unroll
        for (int t = 0; t < 16; t++) {
            float4 t4 = *(float4*)&Cs[rr * LDQ + cc + t * 4];
            t4.x += bias_s[cc + t * 4];     t4.y += bias_s[cc + t * 4 + 1];
            t4.z += bias_s[cc + t * 4 + 2]; t4.w += bias_s[cc + t * 4 + 3];
            CVT4(t4);   // pre-round for fused_attn (tf32 inputs)
            *(float4*)&dst[t * 4] = t4;
        }
    }
}

// ============================================================
// Kernel 2: fused attention, register-resident P, all-tf32 MMAs,
// cp.async double-buffered K/V (loads one chunk ahead).
// ============================================================
__global__ void __launch_bounds__(256, 2)
fused_attn_kernel(const int* __restrict__ mask, float* __restrict__ attn) {
    extern __shared__ float sm[];
    float* Qs    = sm;                       // [128][LDP]
    float* KV    = Qs + 128 * LDP;           // 2 x { K[64][LDP], V[64][LDP] }
    float* biasv = KV + 2 * 2 * 64 * LDP;    // [KHALF]
    float* lsmem = biasv + KHALF;            // [128][2]

    const int tid = threadIdx.x;
    const int w = tid >> 5;
    const int lane = tid & 31;
    const int g = lane >> 2;
    const int t = lane & 3;
    const int bh = blockIdx.y;
    const int b = bh / NH, h = bh % NH;
    const int m0 = blockIdx.x * 128;
    const int half = blockIdx.z;
    const int kbase = half * KHALF;
    const int wm = (w >> 1) * 32;
    const int wcol = w & 1;
    const int wn = wcol * 32;

    const float* qh_head = g_qh + (size_t)bh * SS * DD + (size_t)m0 * DD;
    const float* kh_head = g_kh + (size_t)bh * SS * DD;
    const float* vh_head = g_vh + (size_t)bh * SS * DD;

    const int kvr = tid >> 2, kvc = (tid & 3) * 16;

    // prologue: issue chunk 0 K/V into buffer 0 (pre-rounded tf32 in gmem)
    {
        float* Kb = KV;
        float* Vb = KV + 64 * LDP;
        const float* ksrc = kh_head + (size_t)(kbase + kvr) * DD + kvc;
        const float* vsrc = vh_head + (size_t)(kbase + kvr) * DD + kvc;
        uint32_t kd = (uint32_t)__cvta_generic_to_shared(&Kb[kvr * LDP + kvc]);
        uint32_t vd = (uint32_t)__cvta_generic_to_shared(&Vb[kvr * LDP + kvc]);
        #pragma unroll
        for (int i = 0; i < 4; i++) {
            cp_async16(kd + i * 16, ksrc + i * 4);
            cp_async16(vd + i * 16, vsrc + i * 4);
        }
        CP_COMMIT();
    }

    // load Q tile (already tf32) + mask bias
    #pragma unroll
    for (int jj = 0; jj < 2; jj++) {
        int e = tid + 256 * jj;
        int r = e >> 2, cc = (e & 3) * 16;
        #pragma unroll
        for (int i = 0; i < 4; i++)
            *(float4*)&Qs[r * LDP + cc + i * 4] = *(const float4*)&qh_head[(size_t)r * DD + cc + i * 4];
    }
    #pragma unroll
    for (int i = 0; i < 4; i++) {
        int c = tid + 256 * i;
        biasv[c] = mask[b * SS + kbase + c] ? MASK_B2 : 0.0f;
    }

    const uint32_t* QsU = (const uint32_t*)Qs;

    // attn row pointers for this thread's 4 fragment rows
    float* ar[4];
    {
        const int rows[4] = { wm + g, wm + g + 8, wm + 16 + g, wm + 16 + g + 8 };
        #pragma unroll
        for (int i = 0; i < 4; i++)
            ar[i] = attn + ((size_t)bh * SS + m0 + rows[i]) * SS + kbase;
    }
    const int coff = wn + 2 * t;
    const int shfl1 = (lane & ~3) | (t >> 1);       // source for cols t
    const int shfl2 = shfl1 + 2;                     // source for cols t+4
    const bool oddc = (t & 1);

    float accv[2][8][4] = {};
    float lsum[2][2] = {};

    int ib = 0;
    for (int cl = 0; cl < KHALF; cl += 64, ib ^= 1) {
        // ---- issue prefetch for next chunk into the other buffer ----
        if (cl + 64 < KHALF) {
            float* Kb = KV + (ib ^ 1) * 2 * 64 * LDP;
            float* Vb = Kb + 64 * LDP;
            const float* ksrc = kh_head + (size_t)(kbase + cl + 64 + kvr) * DD + kvc;
            const float* vsrc = vh_head + (size_t)(kbase + cl + 64 + kvr) * DD + kvc;
            uint32_t kd = (uint32_t)__cvta_generic_to_shared(&Kb[kvr * LDP + kvc]);
            uint32_t vd = (uint32_t)__cvta_generic_to_shared(&Vb[kvr * LDP + kvc]);
            #pragma unroll
            for (int i = 0; i < 4; i++) {
                cp_async16(kd + i * 16, ksrc + i * 4);
                cp_async16(vd + i * 16, vsrc + i * 4);
            }
            CP_COMMIT();
            CP_WAIT1();
        } else {
            CP_WAIT0();
        }
        __syncthreads();                                    // B1: buf[ib] visible

        const uint32_t* KsU = (const uint32_t*)(KV + ib * 2 * 64 * LDP);
        const uint32_t* VsU = KsU + 64 * LDP;

        // ---- S = Q @ K^T : warp subtile 32(m) x 32(n), k=64 ----
        float c[2][4][4] = {};
        #pragma unroll
        for (int kk = 0; kk < 8; kk++) {
            uint32_t a[2][4];
            #pragma unroll
            for (int mf = 0; mf < 2; mf++) {
                int base = (wm + mf * 16 + g) * LDP + kk * 8;
                a[mf][0] = QsU[base + t];
                a[mf][1] = QsU[base + 8 * LDP + t];
                a[mf][2] = QsU[base + t + 4];
                a[mf][3] = QsU[base + 8 * LDP + t + 4];
            }
            #pragma unroll
            for (int nf = 0; nf < 4; nf++) {
                int kb = (wn + nf * 8 + g) * LDP + kk * 8;
                uint32_t b0 = KsU[kb + t];
                uint32_t b1 = KsU[kb + t + 4];
                mma_tf32(c[0][nf], a[0][0], a[0][1], a[0][2], a[0][3], b0, b1);
                mma_tf32(c[1][nf], a[1][0], a[1][1], a[1][2], a[1][3], b0, b1);
            }
        }

        // ---- exp in registers + fp32 attn store + row sums ----
        #pragma unroll
        for (int mf = 0; mf < 2; mf++)
            #pragma unroll
            for (int nf = 0; nf < 4; nf++) {
                float2 b2 = *(const float2*)&biasv[cl + coff + nf * 8];
                float p0 = exp2_mufu(fmaf(c[mf][nf][0], SC_L2E, b2.x));
                float p1 = exp2_mufu(fmaf(c[mf][nf][1], SC_L2E, b2.y));
                float p2 = exp2_mufu(fmaf(c[mf][nf][2], SC_L2E, b2.x));
                float p3 = exp2_mufu(fmaf(c[mf][nf][3], SC_L2E, b2.y));
                lsum[mf][0] += p0 + p1;
                lsum[mf][1] += p2 + p3;
                *(float2*)&ar[mf * 2 + 0][cl + coff + nf * 8] = make_float2(p0, p1);
                *(float2*)&ar[mf * 2 + 1][cl + coff + nf * 8] = make_float2(p2, p3);
                c[mf][nf][0] = wmma::__float_to_tf32(p0);
                c[mf][nf][1] = wmma::__float_to_tf32(p1);
                c[mf][nf][2] = wmma::__float_to_tf32(p2);
                c[mf][nf][3] = wmma::__float_to_tf32(p3);
            }

        // ---- AV: per k-step, quad-shuffle P into A-frag, then MMAs ----
        #pragma unroll
        for (int ks = 0; ks < 4; ks++) {
            uint32_t ap[2][4];
            #pragma unroll
            for (int mf = 0; mf < 2; mf++) {
                uint32_t s0 = __float_as_uint(c[mf][ks][0]);
                uint32_t s1 = __float_as_uint(c[mf][ks][1]);
                uint32_t s2 = __float_as_uint(c[mf][ks][2]);
                uint32_t s3 = __float_as_uint(c[mf][ks][3]);
                uint32_t e0 = __shfl_sync(0xFFFFFFFFu, s0, shfl1);
                uint32_t o0 = __shfl_sync(0xFFFFFFFFu, s1, shfl1);
                uint32_t e2 = __shfl_sync(0xFFFFFFFFu, s2, shfl1);
                uint32_t o2 = __shfl_sync(0xFFFFFFFFu, s3, shfl1);
                uint32_t f0 = __shfl_sync(0xFFFFFFFFu, s0, shfl2);
                uint32_t g0 = __shfl_sync(0xFFFFFFFFu, s1, shfl2);
                uint32_t f2 = __shfl_sync(0xFFFFFFFFu, s2, shfl2);
                uint32_t g2 = __shfl_sync(0xFFFFFFFFu, s3, shfl2);
                ap[mf][0] = oddc ? o0 : e0;
                ap[mf][1] = oddc ? o2 : e2;
                ap[mf][2] = oddc ? g0 : f0;
                ap[mf][3] = oddc ? g2 : f2;
            }
            #pragma unroll
            for (int dn = 0; dn < 8; dn++) {
                uint32_t b0 = VsU[(wn + ks * 8 + t) * LDP + dn * 8 + g];
                uint32_t b1 = VsU[(wn + ks * 8 + t + 4) * LDP + dn * 8 + g];
                mma_tf32(accv[0][dn], ap[0][0], ap[0][1], ap[0][2], ap[0][3], b0, b1);
                mma_tf32(accv[1][dn], ap[1][0], ap[1][1], ap[1][2], ap[1][3], b0, b1);
            }
        }
        __syncthreads();                                    // B2: done reading buf[ib]
    }

    // ---- row sums: reduce over t-quad, publish via lsmem ----
    #pragma unroll
    for (int mf = 0; mf < 2; mf++)
        #pragma unroll
        for (int rr = 0; rr < 2; rr++) {
            float v = lsum[mf][rr];
            v += __shfl_xor_sync(0xFFFFFFFFu, v, 1);
            v += __shfl_xor_sync(0xFFFFFFFFu, v, 2);
            if (t == 0)
                lsmem[(wm + mf * 16 + g + rr * 8) * 2 + wcol] = v;
        }

    // ---- combine the two k-partial accv sets via smem (reuse Qs) ----
    if (wcol == 0) {
        #pragma unroll
        for (int mf = 0; mf < 2; mf++)
            #pragma unroll
            for (int dn = 0; dn < 8; dn++) {
                int r0 = wm + mf * 16 + g;
                *(float2*)&Qs[r0 * LDP + dn * 8 + 2 * t]       = make_float2(accv[mf][dn][0], accv[mf][dn][1]);
                *(float2*)&Qs[(r0 + 8) * LDP + dn * 8 + 2 * t] = make_float2(accv[mf][dn][2], accv[mf][dn][3]);
            }
    }
    __syncthreads();
    if (wcol == 1) {
        #pragma unroll
        for (int mf = 0; mf < 2; mf++)
            #pragma unroll
            for (int dn = 0; dn < 8; dn++) {
                int r0 = wm + mf * 16 + g;
                float2* p0 = (float2*)&Qs[r0 * LDP + dn * 8 + 2 * t];
                float2* p1 = (float2*)&Qs[(r0 + 8) * LDP + dn * 8 + 2 * t];
                float2 x0 = *p0, x1 = *p1;
                x0.x += accv[mf][dn][0]; x0.y += accv[mf][dn][1];
                x1.x += accv[mf][dn][2]; x1.y += accv[mf][dn][3];
                *p0 = x0; *p1 = x1;
            }
    }
    if (tid < 128)
        g_lpart[half][bh * SS + m0 + tid] = lsmem[tid * 2] + lsmem[tid * 2 + 1];
    __syncthreads();

    // ---- write unnormalized ctx partial ----
    {
        const int erow = tid >> 1;
        const int cb = (tid & 1) * 4;
        float* dst = &g_cpart[half][((size_t)(b * SS + m0 + erow)) * HH + h * 64];
        #pragma unroll
        for (int i = 0; i < 8; i++) {
            int cc = cb + i * 8;
            *(float4*)&dst[cc] = *(float4*)&Qs[erow * LDP + cc];
        }
    }
}

// ============================================================
// Kernel 3: combine partial AV halves: ctx = (P0+P1)/(l0+l1).
// ============================================================
__global__ void __launch_bounds__(192)
combine_ctx_kernel() {
    const int row = blockIdx.x;           // b*SS + s
    const int b = row >> 11, s = row & 2047;
    __shared__ float inv_s[NH];
    if (threadIdx.x < NH) {
        int li = (b * NH + threadIdx.x) * SS + s;
        inv_s[threadIdx.x] = 1.0f / (g_lpart[0][li] + g_lpart[1][li]);
    }
    __syncthreads();
    const int n = threadIdx.x * 4;
    const float inv = inv_s[n >> 6];
    const size_t base = (size_t)row * HH + n;
    float4 a = *(const float4*)&g_cpart[0][base];
    float4 c = *(const float4*)&g_cpart[1][base];
    a.x = (a.x + c.x) * inv; a.y = (a.y + c.y) * inv;
    a.z = (a.z + c.z) * inv; a.w = (a.w + c.w) * inv;
    *(float4*)&g_ctx[base] = a;
}

// ============================================================
// Kernel 4: attn rescale (block per row, coalesced streaming).
// ============================================================
__global__ void __launch_bounds__(256)
attn_scale_kernel(float* __restrict__ attn) {
    const int row = blockIdx.x;
    const float inv = 1.0f / (g_lpart[0][row] + g_lpart[1][row]);
    float* p = attn + (size_t)row * SS;
    const int t = threadIdx.x;
    #pragma unroll
    for (int i = 0; i < 2; i++) {
        int c = (t + i * 256) * 4;
        float4 v4 = *(float4*)&p[c];
        v4.x *= inv; v4.y *= inv; v4.z *= inv; v4.w *= inv;
        *(float4*)&p[c] = v4;
    }
}

// ============================================================
// Kernel 5: out = ctx @ Wm^T + bm (128x64 tile, 16-k slab).
// ============================================================
__global__ void __launch_bounds__(256)
out_proj_kernel(const float* __restrict__ Wm,
                const float* __restrict__ bm,
                float* __restrict__ out) {
    __shared__ float sbuf[128 * LDP];
    __shared__ float bias_s[64];
    float* As = sbuf;
    float* Bs = sbuf + 128 * LDT;
    float* Cs = sbuf;

    const int tid = threadIdx.x;
    const int w = tid >> 5;
    const int m0 = blockIdx.y * 128, n0 = blockIdx.x * 64;
    const int mw = (w >> 1) * 32, nw = (w & 1) * 32;
    if (tid < 64) bias_s[tid] = bm[n0 + tid];

    FragC acc[2][2];
    #pragma unroll
    for (int i = 0; i < 2; i++)
        #pragma unroll
        for (int j = 0; j < 2; j++) wmma::fill_fragment(acc[i][j], 0.0f);

    for (int k0 = 0; k0 < HH; k0 += 16) {
        #pragma unroll
        for (int jj = 0; jj < 2; jj++) {
            int e = tid + 256 * jj;
            int r = e >> 2, c4 = (e & 3) * 4;
            float4 t4 = *(const float4*)&g_ctx[(size_t)(m0 + r) * HH + k0 + c4];
            CVT4(t4);
            *(float4*)&As[r * LDT + c4] = t4;
        }
        {
            int r = tid >> 2, c4 = (tid & 3) * 4;
            float4 t4 = *(const float4*)&Wm[(size_t)(n0 + r) * HH + k0 + c4];
            CVT4(t4);
            *(float4*)&Bs[r * LDT + c4] = t4;
        }
        __syncthreads();
        #pragma unroll
        for (int kt = 0; kt < 2; kt++) {
            FragA a0, a1; FragBc b0, b1;
            wmma::load_matrix_sync(a0, &As[(mw +  0) * LDT + kt * 8], LDT);
            wmma::load_matrix_sync(a1, &As[(mw + 16) * LDT + kt * 8], LDT);
            wmma::load_matrix_sync(b0, &Bs[(nw +  0) * LDT + kt * 8], LDT);
            wmma::load_matrix_sync(b1, &Bs[(nw + 16) * LDT + kt * 8], LDT);
            wmma::mma_sync(acc[0][0], a0, b0, acc[0][0]);
            wmma::mma_sync(acc[0][1], a0, b1, acc[0][1]);
            wmma::mma_sync(acc[1][0], a1, b0, acc[1][0]);
            wmma::mma_sync(acc[1][1], a1, b1, acc[1][1]);
        }
        __syncthreads();
    }
    #pragma unroll
    for (int i = 0; i < 2; i++)
        #pragma unroll
        for (int j = 0; j < 2; j++)
            wmma::store_matrix_sync(&Cs[(mw + i * 16) * LDP + nw + j * 16], acc[i][j], LDP, wmma::mem_row_major);
    __syncthreads();

    #pragma unroll
    for (int jj = 0; jj < 8; jj++) {
        int e = tid + 256 * jj;
        int r = e >> 4, c4 = (e & 15) * 4;
        float4 t4 = *(float4*)&Cs[r * LDP + c4];
        t4.x += bias_s[c4]; t4.y += bias_s[c4 + 1];
        t4.z += bias_s[c4 + 2]; t4.w += bias_s[c4 + 3];
        *(float4*)&out[(size_t)(m0 + r) * HH + n0 + c4] = t4;
    }
}

// ============================================================
// Host launcher — attn_scale overlapped with combine+out_proj.
// ============================================================
extern "C" void kernel_launch(void* const* d_in, const int* in_sizes, int n_in,
                              void* d_out, int out_size) {
    const float* v    = (const float*)d_in[0];
    const float* k    = (const float*)d_in[1];
    const float* q    = (const float*)d_in[2];
    const int*   mask = (const int*)  d_in[3];
    const float* Wv   = (const float*)d_in[4];
    const float* bv   = (const float*)d_in[5];
    const float* Wk   = (const float*)d_in[6];
    const float* bk   = (const float*)d_in[7];
    const float* Wq   = (const float*)d_in[8];
    const float* bq   = (const float*)d_in[9];
    const float* Wm   = (const float*)d_in[10];
    const float* bm   = (const float*)d_in[11];
    float* out = (float*)d_out;

    float* attn;
    if ((size_t)out_size >= (size_t)OUT_ELEMS + ATTN_ELEMS) {
        attn = out + OUT_ELEMS;
    } else {
        void* p = nullptr;
        cudaGetSymbolAddress(&p, g_attn_scratch);
        attn = (float*)p;
    }

    const int SMEM_GEMM = 2 * 128 * LDS * 4;                                    // 69632
    const int SMEM_FA   = (128 * LDP + 4 * 64 * LDP + KHALF + 256) * 4;         // 109568
    static int init_done = 0;
    static cudaStream_t s2;
    static cudaEvent_t ev_fork, ev_join;
    if (!init_done) {
        cudaFuncSetAttribute(proj_qkv_kernel, cudaFuncAttributeMaxDynamicSharedMemorySize, SMEM_GEMM);
        cudaFuncSetAttribute(fused_attn_kernel, cudaFuncAttributeMaxDynamicSharedMemorySize, SMEM_FA);
        cudaStreamCreateWithFlags(&s2, cudaStreamNonBlocking);
        cudaEventCreateWithFlags(&ev_fork, cudaEventDisableTiming);
        cudaEventCreateWithFlags(&ev_join, cudaEventDisableTiming);
        init_done = 1;
    }

    proj_qkv_kernel<<<dim3(HH / 128, M_PROJ / 128, 3), 256, SMEM_GEMM>>>(q, k, v, Wq, bq, Wk, bk, Wv, bv);
    fused_attn_kernel<<<dim3(SS / 128, BH, 2), 256, SMEM_FA>>>(mask, attn);

    // fork: attn_scale on s2, concurrent with combine+out_proj on default
    cudaEventRecord(ev_fork, 0);
    cudaStreamWaitEvent(s2, ev_fork, 0);
    attn_scale_kernel<<<BH * SS, 256, 0, s2>>>(attn);
    cudaEventRecord(ev_join, s2);

    combine_ctx_kernel<<<BB * SS, 192>>>();
    out_proj_kernel<<<dim3(HH / 64, M_PROJ / 128, 1), 256>>>(Wm, bm, out);

    // join: default stream waits for attn_scale before returning
    cudaStreamWaitEvent(0, ev_join, 0);
}